// round 3
// baseline (speedup 1.0000x reference)
#include <cuda_runtime.h>
#include <mma.h>
#include <math.h>
#include <stdint.h>

using namespace nvcuda;

// ---------------- problem constants ----------------
#define BB     2
#define SEQ    2048
#define DMODEL 2048
#define HKN    16
#define HVN    32
#define DKD    128
#define DVD    128
#define KDIM   2048           // HKN*DKD
#define VDIM   4096           // HVN*DVD
#define CONVD  8192           // 2*KDIM + VDIM
#define BSTOK  (BB*SEQ)       // 4096 tokens

// ---------------- scratch (static device globals; no allocs) ----------------
__device__ float g_mixed[(size_t)BSTOK * CONVD];
__device__ float g_z    [(size_t)BSTOK * VDIM];
__device__ float g_q    [(size_t)BSTOK * KDIM];
__device__ float g_k    [(size_t)BSTOK * KDIM];
__device__ float g_v    [(size_t)BSTOK * VDIM];
__device__ float g_eg   [(size_t)BSTOK * HVN];
__device__ float g_beta [(size_t)BSTOK * HVN];
__device__ float g_core [(size_t)BSTOK * VDIM];   // scan out -> gated (tf32-rounded) in-place
// tf32-rounded GEMM operands
__device__ float g_xr   [(size_t)BSTOK * DMODEL];
__device__ float g_wqkvr[(size_t)DMODEL * CONVD];
__device__ float g_wzr  [(size_t)DMODEL * VDIM];
__device__ float g_woutr[(size_t)VDIM * DMODEL];

// ---------------- cp.async helpers ----------------
__device__ __forceinline__ void cp_async16(void* smem, const void* gptr) {
    uint32_t s = (uint32_t)__cvta_generic_to_shared(smem);
    asm volatile("cp.async.cg.shared.global [%0], [%1], 16;\n" :: "r"(s), "l"(gptr));
}
__device__ __forceinline__ void cp_commit() {
    asm volatile("cp.async.commit_group;\n");
}
template<int N>
__device__ __forceinline__ void cp_wait() {
    asm volatile("cp.async.wait_group %0;\n" :: "n"(N));
}

// =====================================================================
// tf32 rounding (round-to-nearest) of a float array, vectorized.
// =====================================================================
__global__ __launch_bounds__(256) void round_tf32_kernel(
    const float* __restrict__ src, float* __restrict__ dst, int n4)
{
    int i = blockIdx.x * 256 + threadIdx.x;
    if (i < n4) {
        float4 v = ((const float4*)src)[i];
        v.x = wmma::__float_to_tf32(v.x);
        v.y = wmma::__float_to_tf32(v.y);
        v.z = wmma::__float_to_tf32(v.z);
        v.w = wmma::__float_to_tf32(v.w);
        ((float4*)dst)[i] = v;
    }
}

// =====================================================================
// GEMM: C[M,N] = A[M,K] @ B[K,N], row-major, tf32 wmma,
// 3-stage cp.async pipeline. Inputs must be pre-rounded to tf32.
// M%128==0, N%128==0, K%32==0.
// =====================================================================
#define GBM 128
#define GBN 128
#define GBK 32
#define APAD 36     // As row stride (floats), 144B (16B multiple)
#define BPAD 136    // Bs row stride (floats), 544B
#define ASTRIDE (GBM*APAD)   // 4608 floats / stage
#define BSTRIDE (GBK*BPAD)   // 4352 floats / stage
#define STAGES 3
#define GEMM_SMEM_BYTES (STAGES*(ASTRIDE+BSTRIDE)*4)  // 107520

__global__ __launch_bounds__(256) void gemm_tf32(
    const float* __restrict__ A, const float* __restrict__ B,
    float* __restrict__ C, int M, int N, int K)
{
    extern __shared__ float smem[];
    float* AsBase = smem;                       // STAGES * ASTRIDE
    float* BsBase = smem + STAGES * ASTRIDE;    // STAGES * BSTRIDE

    const int tid = threadIdx.x;
    const int bm0 = blockIdx.y * GBM;
    const int bn0 = blockIdx.x * GBN;
    const int wid = tid >> 5;
    const int wm  = (wid >> 2) * 64;
    const int wn  = (wid & 3) * 32;
    const int KT  = K / GBK;

    // per-thread load assignments (4 A-chunks + 4 B-chunks of 16B)
    int ar[4], ac[4], br[4], bc[4];
    #pragma unroll
    for (int t = 0; t < 4; t++) {
        int c = tid + t * 256;
        ar[t] = c >> 3;  ac[t] = (c & 7) * 4;
        br[t] = c >> 5;  bc[t] = (c & 31) * 4;
    }

    auto load_tile = [&](int buf, int kt) {
        const int k0 = kt * GBK;
        float* as = AsBase + buf * ASTRIDE;
        float* bs = BsBase + buf * BSTRIDE;
        #pragma unroll
        for (int t = 0; t < 4; t++)
            cp_async16(&as[ar[t] * APAD + ac[t]],
                       A + (size_t)(bm0 + ar[t]) * K + k0 + ac[t]);
        #pragma unroll
        for (int t = 0; t < 4; t++)
            cp_async16(&bs[br[t] * BPAD + bc[t]],
                       B + (size_t)(k0 + br[t]) * N + bn0 + bc[t]);
        cp_commit();
    };

    wmma::fragment<wmma::accumulator, 16, 16, 8, float> acc[4][2];
    #pragma unroll
    for (int i = 0; i < 4; i++)
        #pragma unroll
        for (int j = 0; j < 2; j++)
            wmma::fill_fragment(acc[i][j], 0.0f);

    // prologue: stages 0,1
    load_tile(0, 0);
    load_tile(1, KT > 1 ? 1 : 0);

    for (int i = 0; i < KT; i++) {
        // issue load for i+2 (clamped -> redundant harmless loads at tail)
        int nkt = i + 2 < KT ? i + 2 : KT - 1;
        load_tile((i + 2) % STAGES, nkt);
        cp_wait<2>();           // buffer i ready
        __syncthreads();

        const float* as = AsBase + (i % STAGES) * ASTRIDE;
        const float* bs = BsBase + (i % STAGES) * BSTRIDE;
        #pragma unroll
        for (int kk = 0; kk < GBK; kk += 8) {
            wmma::fragment<wmma::matrix_a, 16, 16, 8, wmma::precision::tf32, wmma::row_major> af[4];
            wmma::fragment<wmma::matrix_b, 16, 16, 8, wmma::precision::tf32, wmma::row_major> bf[2];
            #pragma unroll
            for (int x = 0; x < 4; x++)
                wmma::load_matrix_sync(af[x], &as[(wm + x * 16) * APAD + kk], APAD);
            #pragma unroll
            for (int y = 0; y < 2; y++)
                wmma::load_matrix_sync(bf[y], &bs[kk * BPAD + wn + y * 16], BPAD);
            #pragma unroll
            for (int x = 0; x < 4; x++)
                #pragma unroll
                for (int y = 0; y < 2; y++)
                    wmma::mma_sync(acc[x][y], af[x], bf[y], acc[x][y]);
        }
        __syncthreads();   // all reads of this buffer done before it is rewritten
    }

    #pragma unroll
    for (int x = 0; x < 4; x++)
        #pragma unroll
        for (int y = 0; y < 2; y++)
            wmma::store_matrix_sync(C + (size_t)(bm0 + wm + x * 16) * N + bn0 + wn + y * 16,
                                    acc[x][y], N, wmma::mem_row_major);
}

// =====================================================================
// b/a projections fused with beta=sigmoid(b), eg=exp(g).
// One block per token, 4 threads per output, quad shfl reduce.
// =====================================================================
__global__ __launch_bounds__(256) void proj_ba_kernel(
    const float* __restrict__ X, const float* __restrict__ wb,
    const float* __restrict__ wa, const float* __restrict__ dt_bias,
    const float* __restrict__ A_log,
    float* __restrict__ beta, float* __restrict__ eg)
{
    __shared__ float xs[DMODEL];
    const int bs = blockIdx.x;
    const int tid = threadIdx.x;
    #pragma unroll
    for (int t = tid; t < DMODEL; t += 256)
        xs[t] = X[(size_t)bs * DMODEL + t];
    __syncthreads();

    const int out  = tid >> 2;   // 0..63
    const int part = tid & 3;
    const bool is_b = (out < 32);
    const int h = is_b ? out : out - 32;
    const float* w = (is_b ? wb : wa) + h;

    float acc = 0.0f;
    #pragma unroll 8
    for (int d = part; d < DMODEL; d += 4)
        acc += xs[d] * w[d * 32];
    acc += __shfl_xor_sync(0xffffffffu, acc, 1);
    acc += __shfl_xor_sync(0xffffffffu, acc, 2);

    if (part == 0) {
        if (is_b) {
            beta[(size_t)bs * HVN + h] = 1.0f / (1.0f + expf(-acc));
        } else {
            float x = acc + dt_bias[h];
            float sp = (x > 20.0f) ? x : log1pf(expf(x));
            eg[(size_t)bs * HVN + h] = expf(-expf(A_log[h]) * sp);
        }
    }
}

// =====================================================================
// conv1d(K=4, causal) + silu + per-head l2norm for q and k.
// =====================================================================
__global__ __launch_bounds__(128) void conv_qk_kernel(const float* __restrict__ conv_w)
{
    const int bs  = blockIdx.x;
    const int hy  = blockIdx.y;
    const bool is_k = (hy >= HKN);
    const int head  = is_k ? hy - HKN : hy;
    const int lane  = threadIdx.x;
    const int c     = (is_k ? KDIM : 0) + head * DKD + lane;
    const int s     = bs % SEQ;

    const float w0 = conv_w[c * 4 + 0];
    const float w1 = conv_w[c * 4 + 1];
    const float w2 = conv_w[c * 4 + 2];
    const float w3 = conv_w[c * 4 + 3];

    const long bsl = bs;
    float acc = w3 * g_mixed[bsl * CONVD + c];
    if (s > 0) acc += w2 * g_mixed[(bsl - 1) * CONVD + c];
    if (s > 1) acc += w1 * g_mixed[(bsl - 2) * CONVD + c];
    if (s > 2) acc += w0 * g_mixed[(bsl - 3) * CONVD + c];

    float val = acc / (1.0f + expf(-acc));   // silu

    float ss2 = val * val;
    #pragma unroll
    for (int o = 16; o > 0; o >>= 1)
        ss2 += __shfl_xor_sync(0xffffffffu, ss2, o);
    __shared__ float red[4];
    if ((lane & 31) == 0) red[lane >> 5] = ss2;
    __syncthreads();
    float tot = red[0] + red[1] + red[2] + red[3];

    float out = val * rsqrtf(tot + 1e-6f);
    if (!is_k) out *= 0.08838834764831845f;  // DK^-0.5 folded into q

    float* dst = is_k ? g_k : g_q;
    dst[(size_t)bs * KDIM + head * DKD + lane] = out;
}

// =====================================================================
// conv1d + silu for v channels.
// =====================================================================
__global__ __launch_bounds__(256) void conv_v_kernel(const float* __restrict__ conv_w)
{
    const size_t idx = (size_t)blockIdx.x * 256 + threadIdx.x;
    const int cv = (int)(idx % VDIM);
    const long bsl = (long)(idx / VDIM);
    const int s = (int)(bsl % SEQ);
    const int c = 2 * KDIM + cv;

    const float w0 = conv_w[c * 4 + 0];
    const float w1 = conv_w[c * 4 + 1];
    const float w2 = conv_w[c * 4 + 2];
    const float w3 = conv_w[c * 4 + 3];

    float acc = w3 * g_mixed[bsl * CONVD + c];
    if (s > 0) acc += w2 * g_mixed[(bsl - 1) * CONVD + c];
    if (s > 1) acc += w1 * g_mixed[(bsl - 2) * CONVD + c];
    if (s > 2) acc += w0 * g_mixed[(bsl - 3) * CONVD + c];

    g_v[idx] = acc / (1.0f + expf(-acc));
}

// =====================================================================
// Gated delta-rule scan: double-buffered smem + register prefetch,
// ONE barrier per step. grid = B*HV*2 = 128 CTAs, 256 threads.
// =====================================================================
__global__ __launch_bounds__(256) void scan_kernel()
{
    const int blk  = blockIdx.x;
    const int half = blk & 1;
    const int hv   = (blk >> 1) & (HVN - 1);
    const int b    = blk >> 6;
    const int kh   = hv >> 1;            // GQA: HV/HK = 2
    const int tid  = threadIdx.x;
    const int vcol = tid >> 2;
    const int s4   = tid & 3;

    __shared__ __align__(16) float sk[2][DKD];
    __shared__ __align__(16) float sq[2][DKD];
    __shared__ float sv[2][64];
    __shared__ float sgb[2][2];

    float St[32];
    #pragma unroll
    for (int i = 0; i < 32; i++) St[i] = 0.0f;

    const size_t bs0 = (size_t)b * SEQ;
    float rA = 0.0f, rV = 0.0f, rG = 0.0f, rB = 0.0f;

    // prologue: load step 0, stage to buffer 0
    {
        const size_t bs = bs0;
        if (tid < 128) rA = g_k[(bs * HKN + kh) * DKD + tid];
        else           rA = g_q[(bs * HKN + kh) * DKD + (tid - 128)];
        if (tid < 64)  rV = g_v[(bs * HVN + hv) * DVD + half * 64 + tid];
        if (tid == 0) { rG = g_eg[bs * HVN + hv]; rB = g_beta[bs * HVN + hv]; }
        if (tid < 128) sk[0][tid] = rA; else sq[0][tid - 128] = rA;
        if (tid < 64)  sv[0][tid] = rV;
        if (tid == 0) { sgb[0][0] = rG; sgb[0][1] = rB; }
    }
    __syncthreads();

    for (int s = 0; s < SEQ; s++) {
        const int p = s & 1;

        // prefetch step s+1 into registers (overlaps with compute below)
        const bool more = (s + 1 < SEQ);
        if (more) {
            const size_t bs = bs0 + s + 1;
            if (tid < 128) rA = g_k[(bs * HKN + kh) * DKD + tid];
            else           rA = g_q[(bs * HKN + kh) * DKD + (tid - 128)];
            if (tid < 64)  rV = g_v[(bs * HVN + hv) * DVD + half * 64 + tid];
            if (tid == 0) { rG = g_eg[bs * HVN + hv]; rB = g_beta[bs * HVN + hv]; }
        }

        const float egv = sgb[p][0];
        const float bt  = sgb[p][1];
        const float4* k4 = (const float4*)(sk[p] + s4 * 32);
        const float4* q4 = (const float4*)(sq[p] + s4 * 32);

        float vold = 0.0f;
        #pragma unroll
        for (int j = 0; j < 8; j++) {
            float4 kk = k4[j];
            St[4*j+0] *= egv; vold += kk.x * St[4*j+0];
            St[4*j+1] *= egv; vold += kk.y * St[4*j+1];
            St[4*j+2] *= egv; vold += kk.z * St[4*j+2];
            St[4*j+3] *= egv; vold += kk.w * St[4*j+3];
        }
        vold += __shfl_xor_sync(0xffffffffu, vold, 1);
        vold += __shfl_xor_sync(0xffffffffu, vold, 2);

        const float delta = (sv[p][vcol] - vold) * bt;

        float o = 0.0f;
        #pragma unroll
        for (int j = 0; j < 8; j++) {
            float4 kk = k4[j];
            float4 qq = q4[j];
            St[4*j+0] += kk.x * delta; o += qq.x * St[4*j+0];
            St[4*j+1] += kk.y * delta; o += qq.y * St[4*j+1];
            St[4*j+2] += kk.z * delta; o += qq.z * St[4*j+2];
            St[4*j+3] += kk.w * delta; o += qq.w * St[4*j+3];
        }
        o += __shfl_xor_sync(0xffffffffu, o, 1);
        o += __shfl_xor_sync(0xffffffffu, o, 2);

        if (s4 == 0)
            g_core[((bs0 + s) * HVN + hv) * DVD + half * 64 + vcol] = o;

        // stage prefetched step into the alternate buffer
        if (more) {
            const int np = p ^ 1;
            if (tid < 128) sk[np][tid] = rA; else sq[np][tid - 128] = rA;
            if (tid < 64)  sv[np][tid] = rV;
            if (tid == 0) { sgb[np][0] = rG; sgb[np][1] = rB; }
        }
        __syncthreads();
    }
}

// =====================================================================
// RMSNorm * norm_weight * silu(z), in-place, output rounded to tf32
// (it feeds GEMM3 via cp.async).
// =====================================================================
__global__ __launch_bounds__(128) void rmsnorm_gate_kernel(const float* __restrict__ nw)
{
    const size_t gidx = blockIdx.x;
    const int lane = threadIdx.x;
    const size_t off = gidx * DVD + lane;

    float c = g_core[off];
    float v2 = c * c;
    #pragma unroll
    for (int o = 16; o > 0; o >>= 1)
        v2 += __shfl_xor_sync(0xffffffffu, v2, o);
    __shared__ float red[4];
    if ((lane & 31) == 0) red[lane >> 5] = v2;
    __syncthreads();
    float mean = (red[0] + red[1] + red[2] + red[3]) * (1.0f / 128.0f);

    float z = g_z[off];
    float sz = z / (1.0f + expf(-z));
    float r = c * rsqrtf(mean + 1e-6f) * nw[lane] * sz;
    g_core[off] = wmma::__float_to_tf32(r);
}

// =====================================================================
// launch
// =====================================================================
extern "C" void kernel_launch(void* const* d_in, const int* in_sizes, int n_in,
                              void* d_out, int out_size)
{
    const float* X        = (const float*)d_in[0];
    const float* w_qkv    = (const float*)d_in[1];
    const float* w_z      = (const float*)d_in[2];
    const float* w_b      = (const float*)d_in[3];
    const float* w_a      = (const float*)d_in[4];
    const float* w_out    = (const float*)d_in[5];
    const float* conv_w   = (const float*)d_in[6];
    const float* dt_bias  = (const float*)d_in[7];
    const float* A_log    = (const float*)d_in[8];
    const float* norm_w   = (const float*)d_in[9];
    float* out = (float*)d_out;

    float *p_mixed, *p_z, *p_core, *p_eg, *p_beta;
    float *p_xr, *p_wqkvr, *p_wzr, *p_woutr;
    cudaGetSymbolAddress((void**)&p_mixed, g_mixed);
    cudaGetSymbolAddress((void**)&p_z,     g_z);
    cudaGetSymbolAddress((void**)&p_core,  g_core);
    cudaGetSymbolAddress((void**)&p_eg,    g_eg);
    cudaGetSymbolAddress((void**)&p_beta,  g_beta);
    cudaGetSymbolAddress((void**)&p_xr,    g_xr);
    cudaGetSymbolAddress((void**)&p_wqkvr, g_wqkvr);
    cudaGetSymbolAddress((void**)&p_wzr,   g_wzr);
    cudaGetSymbolAddress((void**)&p_woutr, g_woutr);

    static int smem_set = 0;
    cudaFuncSetAttribute(gemm_tf32, cudaFuncAttributeMaxDynamicSharedMemorySize, GEMM_SMEM_BYTES);
    (void)smem_set;

    // 0) tf32-round GEMM operands
    {
        int n4;
        n4 = BSTOK * DMODEL / 4;
        round_tf32_kernel<<<(n4 + 255) / 256, 256>>>(X, p_xr, n4);
        n4 = DMODEL * CONVD / 4;
        round_tf32_kernel<<<(n4 + 255) / 256, 256>>>(w_qkv, p_wqkvr, n4);
        n4 = DMODEL * VDIM / 4;
        round_tf32_kernel<<<(n4 + 255) / 256, 256>>>(w_z, p_wzr, n4);
        n4 = VDIM * DMODEL / 4;
        round_tf32_kernel<<<(n4 + 255) / 256, 256>>>(w_out, p_woutr, n4);
    }

    // 1) mixed = X @ w_qkv
    gemm_tf32<<<dim3(CONVD / GBN, BSTOK / GBM), 256, GEMM_SMEM_BYTES>>>(
        p_xr, p_wqkvr, p_mixed, BSTOK, CONVD, DMODEL);
    // 2) z = X @ w_z
    gemm_tf32<<<dim3(VDIM / GBN, BSTOK / GBM), 256, GEMM_SMEM_BYTES>>>(
        p_xr, p_wzr, p_z, BSTOK, VDIM, DMODEL);
    // 3) b/a projections
    proj_ba_kernel<<<BSTOK, 256>>>(X, w_b, w_a, dt_bias, A_log, p_beta, p_eg);
    // 4) conv+silu+l2norm for q,k
    conv_qk_kernel<<<dim3(BSTOK, 2 * HKN), 128>>>(conv_w);
    // 5) conv+silu for v
    conv_v_kernel<<<(BSTOK * (size_t)VDIM) / 256, 256>>>(conv_w);
    // 6) gated delta-rule scan
    scan_kernel<<<BB * HVN * 2, 256>>>();
    // 7) rmsnorm * nw * silu(z) (tf32-rounded output)
    rmsnorm_gate_kernel<<<BSTOK * HVN, 128>>>(norm_w);
    // 8) out = core @ w_out
    gemm_tf32<<<dim3(DMODEL / GBN, BSTOK / GBM), 256, GEMM_SMEM_BYTES>>>(
        p_core, p_woutr, out, BSTOK, DMODEL, VDIM);
}

// round 4
// speedup vs baseline: 1.0011x; 1.0011x over previous
#include <cuda_runtime.h>
#include <mma.h>
#include <math.h>
#include <stdint.h>

using namespace nvcuda;

// ---------------- problem constants ----------------
#define BB     2
#define SEQ    2048
#define DMODEL 2048
#define HKN    16
#define HVN    32
#define DKD    128
#define DVD    128
#define KDIM   2048           // HKN*DKD
#define VDIM   4096           // HVN*DVD
#define CONVD  8192           // 2*KDIM + VDIM
#define BSTOK  (BB*SEQ)       // 4096 tokens

// ---------------- scratch (static device globals; no allocs) ----------------
__device__ float g_mixed[(size_t)BSTOK * CONVD];
__device__ float g_z    [(size_t)BSTOK * VDIM];
__device__ float g_q    [(size_t)BSTOK * KDIM];
__device__ float g_k    [(size_t)BSTOK * KDIM];
__device__ float g_v    [(size_t)BSTOK * VDIM];
__device__ float g_eg   [(size_t)BSTOK * HVN];
__device__ float g_beta [(size_t)BSTOK * HVN];
__device__ float g_core [(size_t)BSTOK * VDIM];   // scan out -> gated (tf32-rounded) in-place
// tf32-rounded GEMM operands
__device__ float g_xr   [(size_t)BSTOK * DMODEL];
__device__ float g_wqkvr[(size_t)DMODEL * CONVD];
__device__ float g_wzr  [(size_t)DMODEL * VDIM];
__device__ float g_woutr[(size_t)VDIM * DMODEL];

// ---------------- cp.async helpers ----------------
__device__ __forceinline__ void cp_async16(void* smem, const void* gptr) {
    uint32_t s = (uint32_t)__cvta_generic_to_shared(smem);
    asm volatile("cp.async.cg.shared.global [%0], [%1], 16;\n" :: "r"(s), "l"(gptr));
}
__device__ __forceinline__ void cp_commit() {
    asm volatile("cp.async.commit_group;\n");
}
template<int N>
__device__ __forceinline__ void cp_wait() {
    asm volatile("cp.async.wait_group %0;\n" :: "n"(N));
}

// =====================================================================
// tf32 rounding (round-to-nearest) of a float array, vectorized.
// =====================================================================
__global__ __launch_bounds__(256) void round_tf32_kernel(
    const float* __restrict__ src, float* __restrict__ dst, int n4)
{
    int i = blockIdx.x * 256 + threadIdx.x;
    if (i < n4) {
        float4 v = ((const float4*)src)[i];
        v.x = wmma::__float_to_tf32(v.x);
        v.y = wmma::__float_to_tf32(v.y);
        v.z = wmma::__float_to_tf32(v.z);
        v.w = wmma::__float_to_tf32(v.w);
        ((float4*)dst)[i] = v;
    }
}

// =====================================================================
// GEMM: C[M,N] = A[M,K] @ B[K,N], row-major, tf32 wmma,
// 3-stage cp.async pipeline. Inputs must be pre-rounded to tf32.
// M%128==0, N%128==0, K%32==0.
// =====================================================================
#define GBM 128
#define GBN 128
#define GBK 32
#define APAD 36     // As row stride (floats), 144B (16B multiple)
#define BPAD 136    // Bs row stride (floats), 544B
#define ASTRIDE (GBM*APAD)   // 4608 floats / stage
#define BSTRIDE (GBK*BPAD)   // 4352 floats / stage
#define STAGES 3
#define GEMM_SMEM_BYTES (STAGES*(ASTRIDE+BSTRIDE)*4)  // 107520

__global__ __launch_bounds__(256) void gemm_tf32(
    const float* __restrict__ A, const float* __restrict__ B,
    float* __restrict__ C, int M, int N, int K)
{
    extern __shared__ float smem[];
    float* AsBase = smem;                       // STAGES * ASTRIDE
    float* BsBase = smem + STAGES * ASTRIDE;    // STAGES * BSTRIDE

    const int tid = threadIdx.x;
    const int bm0 = blockIdx.y * GBM;
    const int bn0 = blockIdx.x * GBN;
    const int wid = tid >> 5;
    const int wm  = (wid >> 2) * 64;
    const int wn  = (wid & 3) * 32;
    const int KT  = K / GBK;

    // per-thread load assignments (4 A-chunks + 4 B-chunks of 16B)
    int ar[4], ac[4], br[4], bc[4];
    #pragma unroll
    for (int t = 0; t < 4; t++) {
        int c = tid + t * 256;
        ar[t] = c >> 3;  ac[t] = (c & 7) * 4;
        br[t] = c >> 5;  bc[t] = (c & 31) * 4;
    }

    auto load_tile = [&](int buf, int kt) {
        const int k0 = kt * GBK;
        float* as = AsBase + buf * ASTRIDE;
        float* bs = BsBase + buf * BSTRIDE;
        #pragma unroll
        for (int t = 0; t < 4; t++)
            cp_async16(&as[ar[t] * APAD + ac[t]],
                       A + (size_t)(bm0 + ar[t]) * K + k0 + ac[t]);
        #pragma unroll
        for (int t = 0; t < 4; t++)
            cp_async16(&bs[br[t] * BPAD + bc[t]],
                       B + (size_t)(k0 + br[t]) * N + bn0 + bc[t]);
        cp_commit();
    };

    wmma::fragment<wmma::accumulator, 16, 16, 8, float> acc[4][2];
    #pragma unroll
    for (int i = 0; i < 4; i++)
        #pragma unroll
        for (int j = 0; j < 2; j++)
            wmma::fill_fragment(acc[i][j], 0.0f);

    // prologue: stages 0,1
    load_tile(0, 0);
    load_tile(1, KT > 1 ? 1 : 0);

    for (int i = 0; i < KT; i++) {
        // issue load for i+2 (clamped -> redundant harmless loads at tail)
        int nkt = i + 2 < KT ? i + 2 : KT - 1;
        load_tile((i + 2) % STAGES, nkt);
        cp_wait<2>();           // buffer i ready
        __syncthreads();

        const float* as = AsBase + (i % STAGES) * ASTRIDE;
        const float* bs = BsBase + (i % STAGES) * BSTRIDE;
        #pragma unroll
        for (int kk = 0; kk < GBK; kk += 8) {
            wmma::fragment<wmma::matrix_a, 16, 16, 8, wmma::precision::tf32, wmma::row_major> af[4];
            wmma::fragment<wmma::matrix_b, 16, 16, 8, wmma::precision::tf32, wmma::row_major> bf[2];
            #pragma unroll
            for (int x = 0; x < 4; x++)
                wmma::load_matrix_sync(af[x], &as[(wm + x * 16) * APAD + kk], APAD);
            #pragma unroll
            for (int y = 0; y < 2; y++)
                wmma::load_matrix_sync(bf[y], &bs[kk * BPAD + wn + y * 16], BPAD);
            #pragma unroll
            for (int x = 0; x < 4; x++)
                #pragma unroll
                for (int y = 0; y < 2; y++)
                    wmma::mma_sync(acc[x][y], af[x], bf[y], acc[x][y]);
        }
        __syncthreads();   // all reads of this buffer done before it is rewritten
    }

    #pragma unroll
    for (int x = 0; x < 4; x++)
        #pragma unroll
        for (int y = 0; y < 2; y++)
            wmma::store_matrix_sync(C + (size_t)(bm0 + wm + x * 16) * N + bn0 + wn + y * 16,
                                    acc[x][y], N, wmma::mem_row_major);
}

// =====================================================================
// b/a projections fused with beta=sigmoid(b), eg=exp(g).
// One block per token, 4 threads per output, quad shfl reduce.
// =====================================================================
__global__ __launch_bounds__(256) void proj_ba_kernel(
    const float* __restrict__ X, const float* __restrict__ wb,
    const float* __restrict__ wa, const float* __restrict__ dt_bias,
    const float* __restrict__ A_log,
    float* __restrict__ beta, float* __restrict__ eg)
{
    __shared__ float xs[DMODEL];
    const int bs = blockIdx.x;
    const int tid = threadIdx.x;
    #pragma unroll
    for (int t = tid; t < DMODEL; t += 256)
        xs[t] = X[(size_t)bs * DMODEL + t];
    __syncthreads();

    const int out  = tid >> 2;   // 0..63
    const int part = tid & 3;
    const bool is_b = (out < 32);
    const int h = is_b ? out : out - 32;
    const float* w = (is_b ? wb : wa) + h;

    float acc = 0.0f;
    #pragma unroll 8
    for (int d = part; d < DMODEL; d += 4)
        acc += xs[d] * w[d * 32];
    acc += __shfl_xor_sync(0xffffffffu, acc, 1);
    acc += __shfl_xor_sync(0xffffffffu, acc, 2);

    if (part == 0) {
        if (is_b) {
            beta[(size_t)bs * HVN + h] = 1.0f / (1.0f + expf(-acc));
        } else {
            float x = acc + dt_bias[h];
            float sp = (x > 20.0f) ? x : log1pf(expf(x));
            eg[(size_t)bs * HVN + h] = expf(-expf(A_log[h]) * sp);
        }
    }
}

// =====================================================================
// conv1d(K=4, causal) + silu + per-head l2norm for q and k.
// =====================================================================
__global__ __launch_bounds__(128) void conv_qk_kernel(const float* __restrict__ conv_w)
{
    const int bs  = blockIdx.x;
    const int hy  = blockIdx.y;
    const bool is_k = (hy >= HKN);
    const int head  = is_k ? hy - HKN : hy;
    const int lane  = threadIdx.x;
    const int c     = (is_k ? KDIM : 0) + head * DKD + lane;
    const int s     = bs % SEQ;

    const float w0 = conv_w[c * 4 + 0];
    const float w1 = conv_w[c * 4 + 1];
    const float w2 = conv_w[c * 4 + 2];
    const float w3 = conv_w[c * 4 + 3];

    const long bsl = bs;
    float acc = w3 * g_mixed[bsl * CONVD + c];
    if (s > 0) acc += w2 * g_mixed[(bsl - 1) * CONVD + c];
    if (s > 1) acc += w1 * g_mixed[(bsl - 2) * CONVD + c];
    if (s > 2) acc += w0 * g_mixed[(bsl - 3) * CONVD + c];

    float val = acc / (1.0f + expf(-acc));   // silu

    float ss2 = val * val;
    #pragma unroll
    for (int o = 16; o > 0; o >>= 1)
        ss2 += __shfl_xor_sync(0xffffffffu, ss2, o);
    __shared__ float red[4];
    if ((lane & 31) == 0) red[lane >> 5] = ss2;
    __syncthreads();
    float tot = red[0] + red[1] + red[2] + red[3];

    float out = val * rsqrtf(tot + 1e-6f);
    if (!is_k) out *= 0.08838834764831845f;  // DK^-0.5 folded into q

    float* dst = is_k ? g_k : g_q;
    dst[(size_t)bs * KDIM + head * DKD + lane] = out;
}

// =====================================================================
// conv1d + silu for v channels.
// =====================================================================
__global__ __launch_bounds__(256) void conv_v_kernel(const float* __restrict__ conv_w)
{
    const size_t idx = (size_t)blockIdx.x * 256 + threadIdx.x;
    const int cv = (int)(idx % VDIM);
    const long bsl = (long)(idx / VDIM);
    const int s = (int)(bsl % SEQ);
    const int c = 2 * KDIM + cv;

    const float w0 = conv_w[c * 4 + 0];
    const float w1 = conv_w[c * 4 + 1];
    const float w2 = conv_w[c * 4 + 2];
    const float w3 = conv_w[c * 4 + 3];

    float acc = w3 * g_mixed[bsl * CONVD + c];
    if (s > 0) acc += w2 * g_mixed[(bsl - 1) * CONVD + c];
    if (s > 1) acc += w1 * g_mixed[(bsl - 2) * CONVD + c];
    if (s > 2) acc += w0 * g_mixed[(bsl - 3) * CONVD + c];

    g_v[idx] = acc / (1.0f + expf(-acc));
}

// =====================================================================
// Gated delta-rule scan: double-buffered smem + register prefetch,
// ONE barrier per step. grid = B*HV*2 = 128 CTAs, 256 threads.
// =====================================================================
__global__ __launch_bounds__(256) void scan_kernel()
{
    const int blk  = blockIdx.x;
    const int half = blk & 1;
    const int hv   = (blk >> 1) & (HVN - 1);
    const int b    = blk >> 6;
    const int kh   = hv >> 1;            // GQA: HV/HK = 2
    const int tid  = threadIdx.x;
    const int vcol = tid >> 2;
    const int s4   = tid & 3;

    __shared__ __align__(16) float sk[2][DKD];
    __shared__ __align__(16) float sq[2][DKD];
    __shared__ float sv[2][64];
    __shared__ float sgb[2][2];

    float St[32];
    #pragma unroll
    for (int i = 0; i < 32; i++) St[i] = 0.0f;

    const size_t bs0 = (size_t)b * SEQ;
    float rA = 0.0f, rV = 0.0f, rG = 0.0f, rB = 0.0f;

    // prologue: load step 0, stage to buffer 0
    {
        const size_t bs = bs0;
        if (tid < 128) rA = g_k[(bs * HKN + kh) * DKD + tid];
        else           rA = g_q[(bs * HKN + kh) * DKD + (tid - 128)];
        if (tid < 64)  rV = g_v[(bs * HVN + hv) * DVD + half * 64 + tid];
        if (tid == 0) { rG = g_eg[bs * HVN + hv]; rB = g_beta[bs * HVN + hv]; }
        if (tid < 128) sk[0][tid] = rA; else sq[0][tid - 128] = rA;
        if (tid < 64)  sv[0][tid] = rV;
        if (tid == 0) { sgb[0][0] = rG; sgb[0][1] = rB; }
    }
    __syncthreads();

    for (int s = 0; s < SEQ; s++) {
        const int p = s & 1;

        // prefetch step s+1 into registers (overlaps with compute below)
        const bool more = (s + 1 < SEQ);
        if (more) {
            const size_t bs = bs0 + s + 1;
            if (tid < 128) rA = g_k[(bs * HKN + kh) * DKD + tid];
            else           rA = g_q[(bs * HKN + kh) * DKD + (tid - 128)];
            if (tid < 64)  rV = g_v[(bs * HVN + hv) * DVD + half * 64 + tid];
            if (tid == 0) { rG = g_eg[bs * HVN + hv]; rB = g_beta[bs * HVN + hv]; }
        }

        const float egv = sgb[p][0];
        const float bt  = sgb[p][1];
        const float4* k4 = (const float4*)(sk[p] + s4 * 32);
        const float4* q4 = (const float4*)(sq[p] + s4 * 32);

        float vold = 0.0f;
        #pragma unroll
        for (int j = 0; j < 8; j++) {
            float4 kk = k4[j];
            St[4*j+0] *= egv; vold += kk.x * St[4*j+0];
            St[4*j+1] *= egv; vold += kk.y * St[4*j+1];
            St[4*j+2] *= egv; vold += kk.z * St[4*j+2];
            St[4*j+3] *= egv; vold += kk.w * St[4*j+3];
        }
        vold += __shfl_xor_sync(0xffffffffu, vold, 1);
        vold += __shfl_xor_sync(0xffffffffu, vold, 2);

        const float delta = (sv[p][vcol] - vold) * bt;

        float o = 0.0f;
        #pragma unroll
        for (int j = 0; j < 8; j++) {
            float4 kk = k4[j];
            float4 qq = q4[j];
            St[4*j+0] += kk.x * delta; o += qq.x * St[4*j+0];
            St[4*j+1] += kk.y * delta; o += qq.y * St[4*j+1];
            St[4*j+2] += kk.z * delta; o += qq.z * St[4*j+2];
            St[4*j+3] += kk.w * delta; o += qq.w * St[4*j+3];
        }
        o += __shfl_xor_sync(0xffffffffu, o, 1);
        o += __shfl_xor_sync(0xffffffffu, o, 2);

        if (s4 == 0)
            g_core[((bs0 + s) * HVN + hv) * DVD + half * 64 + vcol] = o;

        // stage prefetched step into the alternate buffer
        if (more) {
            const int np = p ^ 1;
            if (tid < 128) sk[np][tid] = rA; else sq[np][tid - 128] = rA;
            if (tid < 64)  sv[np][tid] = rV;
            if (tid == 0) { sgb[np][0] = rG; sgb[np][1] = rB; }
        }
        __syncthreads();
    }
}

// =====================================================================
// RMSNorm * norm_weight * silu(z), in-place, output rounded to tf32
// (it feeds GEMM3 via cp.async).
// =====================================================================
__global__ __launch_bounds__(128) void rmsnorm_gate_kernel(const float* __restrict__ nw)
{
    const size_t gidx = blockIdx.x;
    const int lane = threadIdx.x;
    const size_t off = gidx * DVD + lane;

    float c = g_core[off];
    float v2 = c * c;
    #pragma unroll
    for (int o = 16; o > 0; o >>= 1)
        v2 += __shfl_xor_sync(0xffffffffu, v2, o);
    __shared__ float red[4];
    if ((lane & 31) == 0) red[lane >> 5] = v2;
    __syncthreads();
    float mean = (red[0] + red[1] + red[2] + red[3]) * (1.0f / 128.0f);

    float z = g_z[off];
    float sz = z / (1.0f + expf(-z));
    float r = c * rsqrtf(mean + 1e-6f) * nw[lane] * sz;
    g_core[off] = wmma::__float_to_tf32(r);
}

// =====================================================================
// launch
// =====================================================================
extern "C" void kernel_launch(void* const* d_in, const int* in_sizes, int n_in,
                              void* d_out, int out_size)
{
    const float* X        = (const float*)d_in[0];
    const float* w_qkv    = (const float*)d_in[1];
    const float* w_z      = (const float*)d_in[2];
    const float* w_b      = (const float*)d_in[3];
    const float* w_a      = (const float*)d_in[4];
    const float* w_out    = (const float*)d_in[5];
    const float* conv_w   = (const float*)d_in[6];
    const float* dt_bias  = (const float*)d_in[7];
    const float* A_log    = (const float*)d_in[8];
    const float* norm_w   = (const float*)d_in[9];
    float* out = (float*)d_out;

    float *p_mixed, *p_z, *p_core, *p_eg, *p_beta;
    float *p_xr, *p_wqkvr, *p_wzr, *p_woutr;
    cudaGetSymbolAddress((void**)&p_mixed, g_mixed);
    cudaGetSymbolAddress((void**)&p_z,     g_z);
    cudaGetSymbolAddress((void**)&p_core,  g_core);
    cudaGetSymbolAddress((void**)&p_eg,    g_eg);
    cudaGetSymbolAddress((void**)&p_beta,  g_beta);
    cudaGetSymbolAddress((void**)&p_xr,    g_xr);
    cudaGetSymbolAddress((void**)&p_wqkvr, g_wqkvr);
    cudaGetSymbolAddress((void**)&p_wzr,   g_wzr);
    cudaGetSymbolAddress((void**)&p_woutr, g_woutr);

    static int smem_set = 0;
    cudaFuncSetAttribute(gemm_tf32, cudaFuncAttributeMaxDynamicSharedMemorySize, GEMM_SMEM_BYTES);
    (void)smem_set;

    // 0) tf32-round GEMM operands
    {
        int n4;
        n4 = BSTOK * DMODEL / 4;
        round_tf32_kernel<<<(n4 + 255) / 256, 256>>>(X, p_xr, n4);
        n4 = DMODEL * CONVD / 4;
        round_tf32_kernel<<<(n4 + 255) / 256, 256>>>(w_qkv, p_wqkvr, n4);
        n4 = DMODEL * VDIM / 4;
        round_tf32_kernel<<<(n4 + 255) / 256, 256>>>(w_z, p_wzr, n4);
        n4 = VDIM * DMODEL / 4;
        round_tf32_kernel<<<(n4 + 255) / 256, 256>>>(w_out, p_woutr, n4);
    }

    // 1) mixed = X @ w_qkv
    gemm_tf32<<<dim3(CONVD / GBN, BSTOK / GBM), 256, GEMM_SMEM_BYTES>>>(
        p_xr, p_wqkvr, p_mixed, BSTOK, CONVD, DMODEL);
    // 2) z = X @ w_z
    gemm_tf32<<<dim3(VDIM / GBN, BSTOK / GBM), 256, GEMM_SMEM_BYTES>>>(
        p_xr, p_wzr, p_z, BSTOK, VDIM, DMODEL);
    // 3) b/a projections
    proj_ba_kernel<<<BSTOK, 256>>>(X, w_b, w_a, dt_bias, A_log, p_beta, p_eg);
    // 4) conv+silu+l2norm for q,k
    conv_qk_kernel<<<dim3(BSTOK, 2 * HKN), 128>>>(conv_w);
    // 5) conv+silu for v
    conv_v_kernel<<<(BSTOK * (size_t)VDIM) / 256, 256>>>(conv_w);
    // 6) gated delta-rule scan
    scan_kernel<<<BB * HVN * 2, 256>>>();
    // 7) rmsnorm * nw * silu(z) (tf32-rounded output)
    rmsnorm_gate_kernel<<<BSTOK * HVN, 128>>>(norm_w);
    // 8) out = core @ w_out
    gemm_tf32<<<dim3(DMODEL / GBN, BSTOK / GBM), 256, GEMM_SMEM_BYTES>>>(
        p_core, p_woutr, out, BSTOK, DMODEL, VDIM);
}

// round 6
// speedup vs baseline: 1.6516x; 1.6498x over previous
#include <cuda_runtime.h>
#include <cuda_fp16.h>
#include <math.h>
#include <stdint.h>

// ---------------- problem constants ----------------
#define BB     2
#define SEQ    2048
#define DMODEL 2048
#define HKN    16
#define HVN    32
#define DKD    128
#define DVD    128
#define KDIM   2048
#define VDIM   4096
#define CONVD  8192
#define BSTOK  (BB*SEQ)

// ---------------- scratch ----------------
__device__ float  g_mixed[(size_t)BSTOK * CONVD];
__device__ float  g_z    [(size_t)BSTOK * VDIM];
__device__ float  g_q    [(size_t)BSTOK * KDIM];
__device__ float  g_k    [(size_t)BSTOK * KDIM];
__device__ float  g_v    [(size_t)BSTOK * VDIM];
__device__ float  g_eg   [(size_t)BSTOK * HVN];
__device__ float  g_beta [(size_t)BSTOK * HVN];
__device__ float  g_core [(size_t)BSTOK * VDIM];
// fp16 GEMM operands; weights stored TRANSPOSED (K-major: [N, K])
__device__ __half g_xh   [(size_t)BSTOK * DMODEL];
__device__ __half g_wqkvh[(size_t)CONVD * DMODEL];
__device__ __half g_wzh  [(size_t)VDIM * DMODEL];
__device__ __half g_wouth[(size_t)DMODEL * VDIM];
__device__ __half g_coreh[(size_t)BSTOK * VDIM];

// ---------------- ptx helpers ----------------
__device__ __forceinline__ uint32_t smem_u32(const void* p) {
    return (uint32_t)__cvta_generic_to_shared(p);
}
__device__ __forceinline__ void cp16(uint32_t saddr, const void* g) {
    asm volatile("cp.async.cg.shared.global [%0], [%1], 16;\n" :: "r"(saddr), "l"(g));
}
__device__ __forceinline__ void cp_commit() { asm volatile("cp.async.commit_group;\n"); }
template<int N> __device__ __forceinline__ void cp_wait() {
    asm volatile("cp.async.wait_group %0;\n" :: "n"(N));
}
__device__ __forceinline__ void ldsm_x4(uint32_t* r, uint32_t addr) {
    asm volatile("ldmatrix.sync.aligned.m8n8.x4.shared.b16 {%0,%1,%2,%3}, [%4];"
                 : "=r"(r[0]), "=r"(r[1]), "=r"(r[2]), "=r"(r[3]) : "r"(addr));
}
__device__ __forceinline__ void mma16816(float* c, const uint32_t* a, const uint32_t* b) {
    asm volatile(
        "mma.sync.aligned.m16n8k16.row.col.f32.f16.f16.f32 "
        "{%0,%1,%2,%3}, {%4,%5,%6,%7}, {%8,%9}, {%0,%1,%2,%3};"
        : "+f"(c[0]), "+f"(c[1]), "+f"(c[2]), "+f"(c[3])
        : "r"(a[0]), "r"(a[1]), "r"(a[2]), "r"(a[3]), "r"(b[0]), "r"(b[1]));
}

// =====================================================================
// fp16 GEMM: C[M,N] = A[M,K] @ Bt[N,K]^T, fp32 accum.
// 128x128 CTA tile, BK=64 (128B rows, SW128 swizzle), 3-stage cp.async,
// 8 warps, warp tile 64x32, mma.sync m16n8k16 + ldmatrix.
// =====================================================================
#define NSTAGE 3
#define STAGE_BYTES 32768            // A 16KB + B 16KB
#define GEMM_DYN (NSTAGE*STAGE_BYTES + 1024)

__global__ __launch_bounds__(256, 1) void gemm_fp16(
    const __half* __restrict__ A, const __half* __restrict__ Bt,
    float* __restrict__ C, int M, int N, int K)
{
    extern __shared__ __align__(16) uint8_t dyn[];
    const uint32_t dynb = smem_u32(dyn);
    const uint32_t base = (dynb + 1023u) & ~1023u;

    const int tid  = threadIdx.x;
    const int wid  = tid >> 5;
    const int lane = tid & 31;
    const int bm0 = blockIdx.y * 128;
    const int bn0 = blockIdx.x * 128;
    const int wm  = (wid >> 2) * 64;
    const int wn  = (wid & 3) * 32;
    const int KT  = K >> 6;          // 64-elem K tiles

    const __half* Arow = A  + (size_t)bm0 * K;
    const __half* Brow = Bt + (size_t)bn0 * K;

    // per-thread cp.async assignment: 4 chunks of 16B for A, 4 for B
    // chunk c (0..1023): row = c>>3, byte col = (c&7)*16
    auto load_tile = [&](int buf, int kt) {
        const uint32_t ab = base + buf * STAGE_BYTES;
        const uint32_t bb = ab + 16384;
        const int k0 = kt << 6;
        #pragma unroll
        for (int t = 0; t < 4; t++) {
            int c = tid + t * 256;
            int row = c >> 3;
            int cb  = (c & 7) << 4;
            uint32_t off = (uint32_t)(row * 128 + cb);
            uint32_t sw = off ^ ((off >> 3) & 0x70u);
            cp16(ab + sw, Arow + (size_t)row * K + k0 + (cb >> 1));
        }
        #pragma unroll
        for (int t = 0; t < 4; t++) {
            int c = tid + t * 256;
            int row = c >> 3;
            int cb  = (c & 7) << 4;
            uint32_t off = (uint32_t)(row * 128 + cb);
            uint32_t sw = off ^ ((off >> 3) & 0x70u);
            cp16(bb + sw, Brow + (size_t)row * K + k0 + (cb >> 1));
        }
        cp_commit();
    };

    // ldmatrix per-thread address components
    // A x4: lanes 0-15 -> rows m+0..15 @ khalf 0 ; lanes 16-31 -> same rows @ khalf 8
    const int aRowL  = lane & 15;            // + wm + mi*16
    const int aKH2   = (lane >> 4) * 16;     // byte offset of k-half (8 halves = 16B)
    // B x4 (two n8 tiles): lanes0-7: n0:8@k0, 8-15: n0:8@k8, 16-23: n8:16@k0, 24-31: n8:16@k8
    const int bRowL  = ((lane >> 4) & 1) * 8 + (lane & 7);  // + wn + ni2*16
    const int bKH2   = ((lane >> 3) & 1) * 16;

    float acc[4][4][4];
    #pragma unroll
    for (int i = 0; i < 4; i++)
        #pragma unroll
        for (int j = 0; j < 4; j++)
            #pragma unroll
            for (int q = 0; q < 4; q++) acc[i][j][q] = 0.0f;

    load_tile(0, 0);
    load_tile(1, 1);

    for (int i = 0; i < KT; i++) {
        if (i + 2 < KT) { load_tile((i + 2) % NSTAGE, i + 2); cp_wait<1>(); }
        else            { cp_wait<0>(); }
        __syncthreads();

        const uint32_t ab = base + (i % NSTAGE) * STAGE_BYTES;
        const uint32_t bb = ab + 16384;

        #pragma unroll
        for (int ks = 0; ks < 4; ks++) {
            uint32_t af[4][4];
            uint32_t bf[2][4];
            #pragma unroll
            for (int mi = 0; mi < 4; mi++) {
                int row = wm + mi * 16 + aRowL;
                uint32_t cb = (uint32_t)((ks * 32 + aKH2) ^ ((row & 7) << 4));
                ldsm_x4(af[mi], ab + row * 128 + cb);
            }
            #pragma unroll
            for (int ni2 = 0; ni2 < 2; ni2++) {
                int row = wn + ni2 * 16 + bRowL;
                uint32_t cb = (uint32_t)((ks * 32 + bKH2) ^ ((row & 7) << 4));
                ldsm_x4(bf[ni2], bb + row * 128 + cb);
            }
            #pragma unroll
            for (int mi = 0; mi < 4; mi++)
                #pragma unroll
                for (int ni = 0; ni < 4; ni++)
                    mma16816(acc[mi][ni], af[mi], &bf[ni >> 1][(ni & 1) * 2]);
        }
        __syncthreads();
    }

    // epilogue: direct float2 stores
    const int l4 = lane >> 2;
    const int l2 = (lane & 3) * 2;
    #pragma unroll
    for (int mi = 0; mi < 4; mi++) {
        #pragma unroll
        for (int ni = 0; ni < 4; ni++) {
            float* c = acc[mi][ni];
            size_t r = (size_t)(bm0 + wm + mi * 16 + l4) * N + bn0 + wn + ni * 8 + l2;
            *(float2*)(C + r)              = make_float2(c[0], c[1]);
            *(float2*)(C + r + 8 * (size_t)N) = make_float2(c[2], c[3]);
        }
    }
}

// =====================================================================
// prep: fp32 -> fp16 round; and transpose+round (weights -> K-major fp16)
// =====================================================================
__global__ __launch_bounds__(256) void round_f16_kernel(
    const float* __restrict__ src, __half* __restrict__ dst, int n4)
{
    int i = blockIdx.x * 256 + threadIdx.x;
    if (i < n4) {
        float4 v = ((const float4*)src)[i];
        __half2 h0 = __floats2half2_rn(v.x, v.y);
        __half2 h1 = __floats2half2_rn(v.z, v.w);
        ((__half2*)dst)[i * 2]     = h0;
        ((__half2*)dst)[i * 2 + 1] = h1;
    }
}

// src[K,N] fp32 -> dst[N,K] fp16
__global__ __launch_bounds__(256) void transpose_f16(
    const float* __restrict__ src, __half* __restrict__ dst, int K, int N)
{
    __shared__ float tile[32][33];
    const int n0 = blockIdx.x * 32, k0 = blockIdx.y * 32;
    const int tx = threadIdx.x & 31, ty = threadIdx.x >> 5;   // 32x8
    #pragma unroll
    for (int j = 0; j < 32; j += 8)
        tile[ty + j][tx] = src[(size_t)(k0 + ty + j) * N + n0 + tx];
    __syncthreads();
    #pragma unroll
    for (int j = 0; j < 32; j += 8)
        dst[(size_t)(n0 + ty + j) * K + k0 + tx] = __float2half_rn(tile[tx][ty + j]);
}

// =====================================================================
// b/a projections -> beta, exp(g)
// =====================================================================
__global__ __launch_bounds__(256) void proj_ba_kernel(
    const float* __restrict__ X, const float* __restrict__ wb,
    const float* __restrict__ wa, const float* __restrict__ dt_bias,
    const float* __restrict__ A_log,
    float* __restrict__ beta, float* __restrict__ eg)
{
    __shared__ float xs[DMODEL];
    const int bs = blockIdx.x;
    const int tid = threadIdx.x;
    for (int t = tid; t < DMODEL; t += 256)
        xs[t] = X[(size_t)bs * DMODEL + t];
    __syncthreads();

    const int out  = tid >> 2;
    const int part = tid & 3;
    const bool is_b = (out < 32);
    const int h = is_b ? out : out - 32;
    const float* w = (is_b ? wb : wa) + h;

    float acc = 0.0f;
    #pragma unroll 8
    for (int d = part; d < DMODEL; d += 4)
        acc += xs[d] * w[d * 32];
    acc += __shfl_xor_sync(0xffffffffu, acc, 1);
    acc += __shfl_xor_sync(0xffffffffu, acc, 2);

    if (part == 0) {
        if (is_b) {
            beta[(size_t)bs * HVN + h] = 1.0f / (1.0f + expf(-acc));
        } else {
            float x = acc + dt_bias[h];
            float sp = (x > 20.0f) ? x : log1pf(expf(x));
            eg[(size_t)bs * HVN + h] = expf(-expf(A_log[h]) * sp);
        }
    }
}

// =====================================================================
// conv1d(K=4, causal) + silu + per-head l2norm for q and k.
// =====================================================================
__global__ __launch_bounds__(128) void conv_qk_kernel(const float* __restrict__ conv_w)
{
    const int bs  = blockIdx.x;
    const int hy  = blockIdx.y;
    const bool is_k = (hy >= HKN);
    const int head  = is_k ? hy - HKN : hy;
    const int lane  = threadIdx.x;
    const int c     = (is_k ? KDIM : 0) + head * DKD + lane;
    const int s     = bs % SEQ;

    const float w0 = conv_w[c * 4 + 0];
    const float w1 = conv_w[c * 4 + 1];
    const float w2 = conv_w[c * 4 + 2];
    const float w3 = conv_w[c * 4 + 3];

    const long bsl = bs;
    float acc = w3 * g_mixed[bsl * CONVD + c];
    if (s > 0) acc += w2 * g_mixed[(bsl - 1) * CONVD + c];
    if (s > 1) acc += w1 * g_mixed[(bsl - 2) * CONVD + c];
    if (s > 2) acc += w0 * g_mixed[(bsl - 3) * CONVD + c];

    float val = acc / (1.0f + expf(-acc));

    float ss2 = val * val;
    #pragma unroll
    for (int o = 16; o > 0; o >>= 1)
        ss2 += __shfl_xor_sync(0xffffffffu, ss2, o);
    __shared__ float red[4];
    if ((lane & 31) == 0) red[lane >> 5] = ss2;
    __syncthreads();
    float tot = red[0] + red[1] + red[2] + red[3];

    float out = val * rsqrtf(tot + 1e-6f);
    if (!is_k) out *= 0.08838834764831845f;

    float* dst = is_k ? g_k : g_q;
    dst[(size_t)bs * KDIM + head * DKD + lane] = out;
}

// =====================================================================
// conv1d + silu for v channels.
// =====================================================================
__global__ __launch_bounds__(256) void conv_v_kernel(const float* __restrict__ conv_w)
{
    const size_t idx = (size_t)blockIdx.x * 256 + threadIdx.x;
    const int cv = (int)(idx % VDIM);
    const long bsl = (long)(idx / VDIM);
    const int s = (int)(bsl % SEQ);
    const int c = 2 * KDIM + cv;

    const float w0 = conv_w[c * 4 + 0];
    const float w1 = conv_w[c * 4 + 1];
    const float w2 = conv_w[c * 4 + 2];
    const float w3 = conv_w[c * 4 + 3];

    float acc = w3 * g_mixed[bsl * CONVD + c];
    if (s > 0) acc += w2 * g_mixed[(bsl - 1) * CONVD + c];
    if (s > 1) acc += w1 * g_mixed[(bsl - 2) * CONVD + c];
    if (s > 2) acc += w0 * g_mixed[(bsl - 3) * CONVD + c];

    g_v[idx] = acc / (1.0f + expf(-acc));
}

// =====================================================================
// Gated delta-rule scan (double-buffered, 4-way accumulator trees).
// =====================================================================
__global__ __launch_bounds__(256) void scan_kernel()
{
    const int blk  = blockIdx.x;
    const int half = blk & 1;
    const int hv   = (blk >> 1) & (HVN - 1);
    const int b    = blk >> 6;
    const int kh   = hv >> 1;
    const int tid  = threadIdx.x;
    const int vcol = tid >> 2;
    const int s4   = tid & 3;

    __shared__ __align__(16) float sk[2][DKD];
    __shared__ __align__(16) float sq[2][DKD];
    __shared__ float sv[2][64];
    __shared__ float sgb[2][2];

    float St[32];
    #pragma unroll
    for (int i = 0; i < 32; i++) St[i] = 0.0f;

    const size_t bs0 = (size_t)b * SEQ;
    float rA = 0.0f, rV = 0.0f, rG = 0.0f, rB = 0.0f;

    {
        const size_t bs = bs0;
        if (tid < 128) rA = g_k[(bs * HKN + kh) * DKD + tid];
        else           rA = g_q[(bs * HKN + kh) * DKD + (tid - 128)];
        if (tid < 64)  rV = g_v[(bs * HVN + hv) * DVD + half * 64 + tid];
        if (tid == 0) { rG = g_eg[bs * HVN + hv]; rB = g_beta[bs * HVN + hv]; }
        if (tid < 128) sk[0][tid] = rA; else sq[0][tid - 128] = rA;
        if (tid < 64)  sv[0][tid] = rV;
        if (tid == 0) { sgb[0][0] = rG; sgb[0][1] = rB; }
    }
    __syncthreads();

    for (int s = 0; s < SEQ; s++) {
        const int p = s & 1;

        const bool more = (s + 1 < SEQ);
        if (more) {
            const size_t bs = bs0 + s + 1;
            if (tid < 128) rA = g_k[(bs * HKN + kh) * DKD + tid];
            else           rA = g_q[(bs * HKN + kh) * DKD + (tid - 128)];
            if (tid < 64)  rV = g_v[(bs * HVN + hv) * DVD + half * 64 + tid];
            if (tid == 0) { rG = g_eg[bs * HVN + hv]; rB = g_beta[bs * HVN + hv]; }
        }

        const float egv = sgb[p][0];
        const float bt  = sgb[p][1];
        const float4* k4 = (const float4*)(sk[p] + s4 * 32);
        const float4* q4 = (const float4*)(sq[p] + s4 * 32);

        float v0 = 0.f, v1 = 0.f, v2 = 0.f, v3 = 0.f;
        #pragma unroll
        for (int j = 0; j < 8; j++) {
            float4 kk = k4[j];
            St[4*j+0] *= egv; v0 += kk.x * St[4*j+0];
            St[4*j+1] *= egv; v1 += kk.y * St[4*j+1];
            St[4*j+2] *= egv; v2 += kk.z * St[4*j+2];
            St[4*j+3] *= egv; v3 += kk.w * St[4*j+3];
        }
        float vold = (v0 + v1) + (v2 + v3);
        vold += __shfl_xor_sync(0xffffffffu, vold, 1);
        vold += __shfl_xor_sync(0xffffffffu, vold, 2);

        const float delta = (sv[p][vcol] - vold) * bt;

        float o0 = 0.f, o1 = 0.f, o2 = 0.f, o3 = 0.f;
        #pragma unroll
        for (int j = 0; j < 8; j++) {
            float4 kk = k4[j];
            float4 qq = q4[j];
            St[4*j+0] += kk.x * delta; o0 += qq.x * St[4*j+0];
            St[4*j+1] += kk.y * delta; o1 += qq.y * St[4*j+1];
            St[4*j+2] += kk.z * delta; o2 += qq.z * St[4*j+2];
            St[4*j+3] += kk.w * delta; o3 += qq.w * St[4*j+3];
        }
        float o = (o0 + o1) + (o2 + o3);
        o += __shfl_xor_sync(0xffffffffu, o, 1);
        o += __shfl_xor_sync(0xffffffffu, o, 2);

        if (s4 == 0)
            g_core[((bs0 + s) * HVN + hv) * DVD + half * 64 + vcol] = o;

        if (more) {
            const int np = p ^ 1;
            if (tid < 128) sk[np][tid] = rA; else sq[np][tid - 128] = rA;
            if (tid < 64)  sv[np][tid] = rV;
            if (tid == 0) { sgb[np][0] = rG; sgb[np][1] = rB; }
        }
        __syncthreads();
    }
}

// =====================================================================
// RMSNorm * norm_weight * silu(z) -> fp16 core (feeds GEMM3).
// =====================================================================
__global__ __launch_bounds__(128) void rmsnorm_gate_kernel(const float* __restrict__ nw)
{
    const size_t gidx = blockIdx.x;
    const int lane = threadIdx.x;
    const size_t off = gidx * DVD + lane;

    float c = g_core[off];
    float v2 = c * c;
    #pragma unroll
    for (int o = 16; o > 0; o >>= 1)
        v2 += __shfl_xor_sync(0xffffffffu, v2, o);
    __shared__ float red[4];
    if ((lane & 31) == 0) red[lane >> 5] = v2;
    __syncthreads();
    float mean = (red[0] + red[1] + red[2] + red[3]) * (1.0f / 128.0f);

    float z = g_z[off];
    float sz = z / (1.0f + expf(-z));
    float r = c * rsqrtf(mean + 1e-6f) * nw[lane] * sz;
    g_coreh[off] = __float2half_rn(r);
}

// =====================================================================
// launch
// =====================================================================
extern "C" void kernel_launch(void* const* d_in, const int* in_sizes, int n_in,
                              void* d_out, int out_size)
{
    const float* X        = (const float*)d_in[0];
    const float* w_qkv    = (const float*)d_in[1];
    const float* w_z      = (const float*)d_in[2];
    const float* w_b      = (const float*)d_in[3];
    const float* w_a      = (const float*)d_in[4];
    const float* w_out    = (const float*)d_in[5];
    const float* conv_w   = (const float*)d_in[6];
    const float* dt_bias  = (const float*)d_in[7];
    const float* A_log    = (const float*)d_in[8];
    const float* norm_w   = (const float*)d_in[9];
    float* out = (float*)d_out;

    float  *p_mixed, *p_z, *p_eg, *p_beta;
    __half *p_xh, *p_wqkvh, *p_wzh, *p_wouth, *p_coreh;
    cudaGetSymbolAddress((void**)&p_mixed, g_mixed);
    cudaGetSymbolAddress((void**)&p_z,     g_z);
    cudaGetSymbolAddress((void**)&p_eg,    g_eg);
    cudaGetSymbolAddress((void**)&p_beta,  g_beta);
    cudaGetSymbolAddress((void**)&p_xh,    g_xh);
    cudaGetSymbolAddress((void**)&p_wqkvh, g_wqkvh);
    cudaGetSymbolAddress((void**)&p_wzh,   g_wzh);
    cudaGetSymbolAddress((void**)&p_wouth, g_wouth);
    cudaGetSymbolAddress((void**)&p_coreh, g_coreh);

    cudaFuncSetAttribute(gemm_fp16, cudaFuncAttributeMaxDynamicSharedMemorySize, GEMM_DYN);

    // 0) prep: round X to fp16; transpose+round weights to K-major fp16
    {
        int n4 = BSTOK * DMODEL / 4;
        round_f16_kernel<<<(n4 + 255) / 256, 256>>>(X, p_xh, n4);
        transpose_f16<<<dim3(CONVD / 32, DMODEL / 32), 256>>>(w_qkv, p_wqkvh, DMODEL, CONVD);
        transpose_f16<<<dim3(VDIM / 32, DMODEL / 32), 256>>>(w_z, p_wzh, DMODEL, VDIM);
        transpose_f16<<<dim3(DMODEL / 32, VDIM / 32), 256>>>(w_out, p_wouth, VDIM, DMODEL);
    }

    // 1) mixed = X @ w_qkv   (M=4096, N=8192, K=2048)
    gemm_fp16<<<dim3(CONVD / 128, BSTOK / 128), 256, GEMM_DYN>>>(
        p_xh, p_wqkvh, p_mixed, BSTOK, CONVD, DMODEL);
    // 2) z = X @ w_z         (M=4096, N=4096, K=2048)
    gemm_fp16<<<dim3(VDIM / 128, BSTOK / 128), 256, GEMM_DYN>>>(
        p_xh, p_wzh, p_z, BSTOK, VDIM, DMODEL);
    // 3) b/a projections
    proj_ba_kernel<<<BSTOK, 256>>>(X, w_b, w_a, dt_bias, A_log, p_beta, p_eg);
    // 4) conv+silu+l2norm q,k
    conv_qk_kernel<<<dim3(BSTOK, 2 * HKN), 128>>>(conv_w);
    // 5) conv+silu v
    conv_v_kernel<<<(BSTOK * (size_t)VDIM) / 256, 256>>>(conv_w);
    // 6) gated delta-rule scan
    scan_kernel<<<BB * HVN * 2, 256>>>();
    // 7) rmsnorm * nw * silu(z) -> fp16 core
    rmsnorm_gate_kernel<<<BSTOK * HVN, 128>>>(norm_w);
    // 8) out = core @ w_out  (M=4096, N=2048, K=4096)
    gemm_fp16<<<dim3(DMODEL / 128, BSTOK / 128), 256, GEMM_DYN>>>(
        p_coreh, p_wouth, out, BSTOK, DMODEL, VDIM);
}

// round 7
// speedup vs baseline: 1.7621x; 1.0669x over previous
#include <cuda_runtime.h>
#include <cuda_fp16.h>
#include <math.h>
#include <stdint.h>

// ---------------- problem constants ----------------
#define BB     2
#define SEQ    2048
#define DMODEL 2048
#define HKN    16
#define HVN    32
#define DKD    128
#define DVD    128
#define KDIM   2048
#define VDIM   4096
#define CONVD  8192
#define BSTOK  (BB*SEQ)

// ---------------- scratch ----------------
__device__ float  g_mixed[(size_t)BSTOK * CONVD];
__device__ float  g_z    [(size_t)BSTOK * VDIM];
__device__ float  g_q    [(size_t)BSTOK * KDIM];
__device__ float  g_k    [(size_t)BSTOK * KDIM];
__device__ float  g_v    [(size_t)BSTOK * VDIM];
__device__ float  g_eg   [(size_t)BSTOK * HVN];
__device__ float  g_beta [(size_t)BSTOK * HVN];
__device__ float  g_core [(size_t)BSTOK * VDIM];
// fp16 GEMM operands; weights stored TRANSPOSED (K-major: [N, K])
__device__ __half g_xh   [(size_t)BSTOK * DMODEL];
__device__ __half g_wqkvh[(size_t)CONVD * DMODEL];
__device__ __half g_wzh  [(size_t)VDIM * DMODEL];
__device__ __half g_wouth[(size_t)DMODEL * VDIM];
__device__ __half g_coreh[(size_t)BSTOK * VDIM];

// ---------------- ptx helpers ----------------
__device__ __forceinline__ uint32_t smem_u32(const void* p) {
    return (uint32_t)__cvta_generic_to_shared(p);
}
__device__ __forceinline__ void cp16(uint32_t saddr, const void* g) {
    asm volatile("cp.async.cg.shared.global [%0], [%1], 16;\n" :: "r"(saddr), "l"(g));
}
__device__ __forceinline__ void cp_commit() { asm volatile("cp.async.commit_group;\n"); }
template<int N> __device__ __forceinline__ void cp_wait() {
    asm volatile("cp.async.wait_group %0;\n" :: "n"(N));
}
__device__ __forceinline__ void ldsm_x4(uint32_t* r, uint32_t addr) {
    asm volatile("ldmatrix.sync.aligned.m8n8.x4.shared.b16 {%0,%1,%2,%3}, [%4];"
                 : "=r"(r[0]), "=r"(r[1]), "=r"(r[2]), "=r"(r[3]) : "r"(addr));
}
__device__ __forceinline__ void mma16816(float* c, const uint32_t* a, const uint32_t* b) {
    asm volatile(
        "mma.sync.aligned.m16n8k16.row.col.f32.f16.f16.f32 "
        "{%0,%1,%2,%3}, {%4,%5,%6,%7}, {%8,%9}, {%0,%1,%2,%3};"
        : "+f"(c[0]), "+f"(c[1]), "+f"(c[2]), "+f"(c[3])
        : "r"(a[0]), "r"(a[1]), "r"(a[2]), "r"(a[3]), "r"(b[0]), "r"(b[1]));
}

// =====================================================================
// fp16 GEMM: C[M,N] = A[M,K] @ Bt[N,K]^T, fp32 accum.
// CTA tile 128x256, warp tile 64x64 (8 warps, 2x4), BK=64 (SW128 rows),
// 4-stage cp.async pipeline with ONE __syncthreads per K-tile.
// =====================================================================
#define NSTAGE 4
#define A_STAGE_BYTES 16384          // 128 rows * 128B
#define B_STAGE_BYTES 32768          // 256 rows * 128B
#define STAGE_BYTES   (A_STAGE_BYTES + B_STAGE_BYTES)   // 49152
#define GEMM_DYN (NSTAGE*STAGE_BYTES + 1024)            // 197632

__global__ __launch_bounds__(256, 1) void gemm_fp16(
    const __half* __restrict__ A, const __half* __restrict__ Bt,
    float* __restrict__ C, int M, int N, int K)
{
    extern __shared__ __align__(16) uint8_t dyn[];
    const uint32_t dynb = smem_u32(dyn);
    const uint32_t base = (dynb + 1023u) & ~1023u;

    const int tid  = threadIdx.x;
    const int wid  = tid >> 5;
    const int lane = tid & 31;
    const int bm0 = blockIdx.y * 128;
    const int bn0 = blockIdx.x * 256;
    const int wm  = (wid & 1) * 64;          // 2 row-blocks
    const int wn  = (wid >> 1) * 64;         // 4 col-blocks
    const int KT  = K >> 6;                  // 64-elem K tiles

    const __half* Arow = A  + (size_t)bm0 * K;
    const __half* Brow = Bt + (size_t)bn0 * K;

    // cp.async tile load: A 128x64h (1024 x16B chunks), B 256x64h (2048 chunks)
    auto load_tile = [&](int buf, int kt) {
        const uint32_t ab = base + buf * STAGE_BYTES;
        const uint32_t bb = ab + A_STAGE_BYTES;
        const int k0 = kt << 6;
        #pragma unroll
        for (int t = 0; t < 4; t++) {
            int c = tid + t * 256;
            int row = c >> 3;
            int cb  = (c & 7) << 4;
            uint32_t off = (uint32_t)(row * 128 + cb);
            uint32_t sw = off ^ ((off >> 3) & 0x70u);
            cp16(ab + sw, Arow + (size_t)row * K + k0 + (cb >> 1));
        }
        #pragma unroll
        for (int t = 0; t < 8; t++) {
            int c = tid + t * 256;
            int row = c >> 3;
            int cb  = (c & 7) << 4;
            uint32_t off = (uint32_t)(row * 128 + cb);
            uint32_t sw = off ^ ((off >> 3) & 0x70u);
            cp16(bb + sw, Brow + (size_t)row * K + k0 + (cb >> 1));
        }
        cp_commit();
    };

    // ldmatrix per-thread components (validated in round 6)
    const int aRowL = lane & 15;
    const int aKH2  = (lane >> 4) * 16;
    const int bRowL = ((lane >> 4) & 1) * 8 + (lane & 7);
    const int bKH2  = ((lane >> 3) & 1) * 16;

    float acc[4][8][4];
    #pragma unroll
    for (int i = 0; i < 4; i++)
        #pragma unroll
        for (int j = 0; j < 8; j++)
            #pragma unroll
            for (int q = 0; q < 4; q++) acc[i][j][q] = 0.0f;

    // prologue: 3 tiles in flight
    load_tile(0, 0);
    load_tile(1, KT > 1 ? 1 : 0);
    load_tile(2, KT > 2 ? 2 : 0);

    for (int i = 0; i < KT; i++) {
        cp_wait<2>();            // tile i resident
        __syncthreads();         // all warps done with tile i-1 -> buf (i+3)%4 free

        if (i + 3 < KT) load_tile((i + 3) % NSTAGE, i + 3);
        else            cp_commit();   // keep group accounting aligned

        const uint32_t ab = base + (i % NSTAGE) * STAGE_BYTES;
        const uint32_t bb = ab + A_STAGE_BYTES;

        #pragma unroll
        for (int ks = 0; ks < 4; ks++) {
            uint32_t af[4][4];
            uint32_t bf[4][4];
            #pragma unroll
            for (int mi = 0; mi < 4; mi++) {
                int row = wm + mi * 16 + aRowL;
                uint32_t cb = (uint32_t)((ks * 32 + aKH2) ^ ((row & 7) << 4));
                ldsm_x4(af[mi], ab + row * 128 + cb);
            }
            #pragma unroll
            for (int ni2 = 0; ni2 < 4; ni2++) {
                int row = wn + ni2 * 16 + bRowL;
                uint32_t cb = (uint32_t)((ks * 32 + bKH2) ^ ((row & 7) << 4));
                ldsm_x4(bf[ni2], bb + row * 128 + cb);
            }
            #pragma unroll
            for (int mi = 0; mi < 4; mi++)
                #pragma unroll
                for (int ni = 0; ni < 8; ni++)
                    mma16816(acc[mi][ni], af[mi], &bf[ni >> 1][(ni & 1) * 2]);
        }
    }

    // epilogue: direct float2 stores
    const int l4 = lane >> 2;
    const int l2 = (lane & 3) * 2;
    #pragma unroll
    for (int mi = 0; mi < 4; mi++) {
        #pragma unroll
        for (int ni = 0; ni < 8; ni++) {
            float* c = acc[mi][ni];
            size_t r = (size_t)(bm0 + wm + mi * 16 + l4) * N + bn0 + wn + ni * 8 + l2;
            *(float2*)(C + r)                 = make_float2(c[0], c[1]);
            *(float2*)(C + r + 8 * (size_t)N) = make_float2(c[2], c[3]);
        }
    }
}

// =====================================================================
// prep: fp32 -> fp16 round; transpose (weights -> K-major fp16)
// =====================================================================
__global__ __launch_bounds__(256) void round_f16_kernel(
    const float* __restrict__ src, __half* __restrict__ dst, int n4)
{
    int i = blockIdx.x * 256 + threadIdx.x;
    if (i < n4) {
        float4 v = ((const float4*)src)[i];
        ((__half2*)dst)[i * 2]     = __floats2half2_rn(v.x, v.y);
        ((__half2*)dst)[i * 2 + 1] = __floats2half2_rn(v.z, v.w);
    }
}

// src[K,N] fp32 -> dst[N,K] fp16
__global__ __launch_bounds__(256) void transpose_f16(
    const float* __restrict__ src, __half* __restrict__ dst, int K, int N)
{
    __shared__ float tile[32][33];
    const int n0 = blockIdx.x * 32, k0 = blockIdx.y * 32;
    const int tx = threadIdx.x & 31, ty = threadIdx.x >> 5;   // 32x8
    #pragma unroll
    for (int j = 0; j < 32; j += 8)
        tile[ty + j][tx] = src[(size_t)(k0 + ty + j) * N + n0 + tx];
    __syncthreads();
    #pragma unroll
    for (int j = 0; j < 32; j += 8)
        dst[(size_t)(n0 + ty + j) * K + k0 + tx] = __float2half_rn(tile[tx][ty + j]);
}

// =====================================================================
// b/a projections -> beta, exp(g)
// =====================================================================
__global__ __launch_bounds__(256) void proj_ba_kernel(
    const float* __restrict__ X, const float* __restrict__ wb,
    const float* __restrict__ wa, const float* __restrict__ dt_bias,
    const float* __restrict__ A_log,
    float* __restrict__ beta, float* __restrict__ eg)
{
    __shared__ float xs[DMODEL];
    const int bs = blockIdx.x;
    const int tid = threadIdx.x;
    for (int t = tid; t < DMODEL; t += 256)
        xs[t] = X[(size_t)bs * DMODEL + t];
    __syncthreads();

    const int out  = tid >> 2;
    const int part = tid & 3;
    const bool is_b = (out < 32);
    const int h = is_b ? out : out - 32;
    const float* w = (is_b ? wb : wa) + h;

    float acc = 0.0f;
    #pragma unroll 8
    for (int d = part; d < DMODEL; d += 4)
        acc += xs[d] * w[d * 32];
    acc += __shfl_xor_sync(0xffffffffu, acc, 1);
    acc += __shfl_xor_sync(0xffffffffu, acc, 2);

    if (part == 0) {
        if (is_b) {
            beta[(size_t)bs * HVN + h] = 1.0f / (1.0f + expf(-acc));
        } else {
            float x = acc + dt_bias[h];
            float sp = (x > 20.0f) ? x : log1pf(expf(x));
            eg[(size_t)bs * HVN + h] = expf(-expf(A_log[h]) * sp);
        }
    }
}

// =====================================================================
// conv1d(K=4, causal) + silu + per-head l2norm for q and k.
// =====================================================================
__global__ __launch_bounds__(128) void conv_qk_kernel(const float* __restrict__ conv_w)
{
    const int bs  = blockIdx.x;
    const int hy  = blockIdx.y;
    const bool is_k = (hy >= HKN);
    const int head  = is_k ? hy - HKN : hy;
    const int lane  = threadIdx.x;
    const int c     = (is_k ? KDIM : 0) + head * DKD + lane;
    const int s     = bs % SEQ;

    const float w0 = conv_w[c * 4 + 0];
    const float w1 = conv_w[c * 4 + 1];
    const float w2 = conv_w[c * 4 + 2];
    const float w3 = conv_w[c * 4 + 3];

    const long bsl = bs;
    float acc = w3 * g_mixed[bsl * CONVD + c];
    if (s > 0) acc += w2 * g_mixed[(bsl - 1) * CONVD + c];
    if (s > 1) acc += w1 * g_mixed[(bsl - 2) * CONVD + c];
    if (s > 2) acc += w0 * g_mixed[(bsl - 3) * CONVD + c];

    float val = acc / (1.0f + expf(-acc));

    float ss2 = val * val;
    #pragma unroll
    for (int o = 16; o > 0; o >>= 1)
        ss2 += __shfl_xor_sync(0xffffffffu, ss2, o);
    __shared__ float red[4];
    if ((lane & 31) == 0) red[lane >> 5] = ss2;
    __syncthreads();
    float tot = red[0] + red[1] + red[2] + red[3];

    float out = val * rsqrtf(tot + 1e-6f);
    if (!is_k) out *= 0.08838834764831845f;

    float* dst = is_k ? g_k : g_q;
    dst[(size_t)bs * KDIM + head * DKD + lane] = out;
}

// =====================================================================
// conv1d + silu for v channels.
// =====================================================================
__global__ __launch_bounds__(256) void conv_v_kernel(const float* __restrict__ conv_w)
{
    const size_t idx = (size_t)blockIdx.x * 256 + threadIdx.x;
    const int cv = (int)(idx % VDIM);
    const long bsl = (long)(idx / VDIM);
    const int s = (int)(bsl % SEQ);
    const int c = 2 * KDIM + cv;

    const float w0 = conv_w[c * 4 + 0];
    const float w1 = conv_w[c * 4 + 1];
    const float w2 = conv_w[c * 4 + 2];
    const float w3 = conv_w[c * 4 + 3];

    float acc = w3 * g_mixed[bsl * CONVD + c];
    if (s > 0) acc += w2 * g_mixed[(bsl - 1) * CONVD + c];
    if (s > 1) acc += w1 * g_mixed[(bsl - 2) * CONVD + c];
    if (s > 2) acc += w0 * g_mixed[(bsl - 3) * CONVD + c];

    g_v[idx] = acc / (1.0f + expf(-acc));
}

// =====================================================================
// Gated delta-rule scan (double-buffered, 4-way accumulator trees).
// =====================================================================
__global__ __launch_bounds__(256) void scan_kernel()
{
    const int blk  = blockIdx.x;
    const int half = blk & 1;
    const int hv   = (blk >> 1) & (HVN - 1);
    const int b    = blk >> 6;
    const int kh   = hv >> 1;
    const int tid  = threadIdx.x;
    const int vcol = tid >> 2;
    const int s4   = tid & 3;

    __shared__ __align__(16) float sk[2][DKD];
    __shared__ __align__(16) float sq[2][DKD];
    __shared__ float sv[2][64];
    __shared__ float sgb[2][2];

    float St[32];
    #pragma unroll
    for (int i = 0; i < 32; i++) St[i] = 0.0f;

    const size_t bs0 = (size_t)b * SEQ;
    float rA = 0.0f, rV = 0.0f, rG = 0.0f, rB = 0.0f;

    {
        const size_t bs = bs0;
        if (tid < 128) rA = g_k[(bs * HKN + kh) * DKD + tid];
        else           rA = g_q[(bs * HKN + kh) * DKD + (tid - 128)];
        if (tid < 64)  rV = g_v[(bs * HVN + hv) * DVD + half * 64 + tid];
        if (tid == 0) { rG = g_eg[bs * HVN + hv]; rB = g_beta[bs * HVN + hv]; }
        if (tid < 128) sk[0][tid] = rA; else sq[0][tid - 128] = rA;
        if (tid < 64)  sv[0][tid] = rV;
        if (tid == 0) { sgb[0][0] = rG; sgb[0][1] = rB; }
    }
    __syncthreads();

    for (int s = 0; s < SEQ; s++) {
        const int p = s & 1;

        const bool more = (s + 1 < SEQ);
        if (more) {
            const size_t bs = bs0 + s + 1;
            if (tid < 128) rA = g_k[(bs * HKN + kh) * DKD + tid];
            else           rA = g_q[(bs * HKN + kh) * DKD + (tid - 128)];
            if (tid < 64)  rV = g_v[(bs * HVN + hv) * DVD + half * 64 + tid];
            if (tid == 0) { rG = g_eg[bs * HVN + hv]; rB = g_beta[bs * HVN + hv]; }
        }

        const float egv = sgb[p][0];
        const float bt  = sgb[p][1];
        const float4* k4 = (const float4*)(sk[p] + s4 * 32);
        const float4* q4 = (const float4*)(sq[p] + s4 * 32);

        float v0 = 0.f, v1 = 0.f, v2 = 0.f, v3 = 0.f;
        #pragma unroll
        for (int j = 0; j < 8; j++) {
            float4 kk = k4[j];
            St[4*j+0] *= egv; v0 += kk.x * St[4*j+0];
            St[4*j+1] *= egv; v1 += kk.y * St[4*j+1];
            St[4*j+2] *= egv; v2 += kk.z * St[4*j+2];
            St[4*j+3] *= egv; v3 += kk.w * St[4*j+3];
        }
        float vold = (v0 + v1) + (v2 + v3);
        vold += __shfl_xor_sync(0xffffffffu, vold, 1);
        vold += __shfl_xor_sync(0xffffffffu, vold, 2);

        const float delta = (sv[p][vcol] - vold) * bt;

        float o0 = 0.f, o1 = 0.f, o2 = 0.f, o3 = 0.f;
        #pragma unroll
        for (int j = 0; j < 8; j++) {
            float4 kk = k4[j];
            float4 qq = q4[j];
            St[4*j+0] += kk.x * delta; o0 += qq.x * St[4*j+0];
            St[4*j+1] += kk.y * delta; o1 += qq.y * St[4*j+1];
            St[4*j+2] += kk.z * delta; o2 += qq.z * St[4*j+2];
            St[4*j+3] += kk.w * delta; o3 += qq.w * St[4*j+3];
        }
        float o = (o0 + o1) + (o2 + o3);
        o += __shfl_xor_sync(0xffffffffu, o, 1);
        o += __shfl_xor_sync(0xffffffffu, o, 2);

        if (s4 == 0)
            g_core[((bs0 + s) * HVN + hv) * DVD + half * 64 + vcol] = o;

        if (more) {
            const int np = p ^ 1;
            if (tid < 128) sk[np][tid] = rA; else sq[np][tid - 128] = rA;
            if (tid < 64)  sv[np][tid] = rV;
            if (tid == 0) { sgb[np][0] = rG; sgb[np][1] = rB; }
        }
        __syncthreads();
    }
}

// =====================================================================
// RMSNorm * norm_weight * silu(z) -> fp16 core (feeds GEMM3).
// =====================================================================
__global__ __launch_bounds__(128) void rmsnorm_gate_kernel(const float* __restrict__ nw)
{
    const size_t gidx = blockIdx.x;
    const int lane = threadIdx.x;
    const size_t off = gidx * DVD + lane;

    float c = g_core[off];
    float v2 = c * c;
    #pragma unroll
    for (int o = 16; o > 0; o >>= 1)
        v2 += __shfl_xor_sync(0xffffffffu, v2, o);
    __shared__ float red[4];
    if ((lane & 31) == 0) red[lane >> 5] = v2;
    __syncthreads();
    float mean = (red[0] + red[1] + red[2] + red[3]) * (1.0f / 128.0f);

    float z = g_z[off];
    float sz = z / (1.0f + expf(-z));
    float r = c * rsqrtf(mean + 1e-6f) * nw[lane] * sz;
    g_coreh[off] = __float2half_rn(r);
}

// =====================================================================
// launch
// =====================================================================
extern "C" void kernel_launch(void* const* d_in, const int* in_sizes, int n_in,
                              void* d_out, int out_size)
{
    const float* X        = (const float*)d_in[0];
    const float* w_qkv    = (const float*)d_in[1];
    const float* w_z      = (const float*)d_in[2];
    const float* w_b      = (const float*)d_in[3];
    const float* w_a      = (const float*)d_in[4];
    const float* w_out    = (const float*)d_in[5];
    const float* conv_w   = (const float*)d_in[6];
    const float* dt_bias  = (const float*)d_in[7];
    const float* A_log    = (const float*)d_in[8];
    const float* norm_w   = (const float*)d_in[9];
    float* out = (float*)d_out;

    float  *p_mixed, *p_z, *p_eg, *p_beta;
    __half *p_xh, *p_wqkvh, *p_wzh, *p_wouth, *p_coreh;
    cudaGetSymbolAddress((void**)&p_mixed, g_mixed);
    cudaGetSymbolAddress((void**)&p_z,     g_z);
    cudaGetSymbolAddress((void**)&p_eg,    g_eg);
    cudaGetSymbolAddress((void**)&p_beta,  g_beta);
    cudaGetSymbolAddress((void**)&p_xh,    g_xh);
    cudaGetSymbolAddress((void**)&p_wqkvh, g_wqkvh);
    cudaGetSymbolAddress((void**)&p_wzh,   g_wzh);
    cudaGetSymbolAddress((void**)&p_wouth, g_wouth);
    cudaGetSymbolAddress((void**)&p_coreh, g_coreh);

    cudaFuncSetAttribute(gemm_fp16, cudaFuncAttributeMaxDynamicSharedMemorySize, GEMM_DYN);

    // 0) prep: round X to fp16; transpose weights to K-major fp16
    {
        int n4 = BSTOK * DMODEL / 4;
        round_f16_kernel<<<(n4 + 255) / 256, 256>>>(X, p_xh, n4);
        transpose_f16<<<dim3(CONVD / 32, DMODEL / 32), 256>>>(w_qkv, p_wqkvh, DMODEL, CONVD);
        transpose_f16<<<dim3(VDIM / 32, DMODEL / 32), 256>>>(w_z, p_wzh, DMODEL, VDIM);
        transpose_f16<<<dim3(DMODEL / 32, VDIM / 32), 256>>>(w_out, p_wouth, VDIM, DMODEL);
    }

    // 1) mixed = X @ w_qkv   (M=4096, N=8192, K=2048)
    gemm_fp16<<<dim3(CONVD / 256, BSTOK / 128), 256, GEMM_DYN>>>(
        p_xh, p_wqkvh, p_mixed, BSTOK, CONVD, DMODEL);
    // 2) z = X @ w_z         (M=4096, N=4096, K=2048)
    gemm_fp16<<<dim3(VDIM / 256, BSTOK / 128), 256, GEMM_DYN>>>(
        p_xh, p_wzh, p_z, BSTOK, VDIM, DMODEL);
    // 3) b/a projections
    proj_ba_kernel<<<BSTOK, 256>>>(X, w_b, w_a, dt_bias, A_log, p_beta, p_eg);
    // 4) conv+silu+l2norm q,k
    conv_qk_kernel<<<dim3(BSTOK, 2 * HKN), 128>>>(conv_w);
    // 5) conv+silu v
    conv_v_kernel<<<(BSTOK * (size_t)VDIM) / 256, 256>>>(conv_w);
    // 6) gated delta-rule scan
    scan_kernel<<<BB * HVN * 2, 256>>>();
    // 7) rmsnorm * nw * silu(z) -> fp16 core
    rmsnorm_gate_kernel<<<BSTOK * HVN, 128>>>(norm_w);
    // 8) out = core @ w_out  (M=4096, N=2048, K=4096)
    gemm_fp16<<<dim3(DMODEL / 256, BSTOK / 128), 256, GEMM_DYN>>>(
        p_coreh, p_wouth, out, BSTOK, DMODEL, VDIM);
}

// round 8
// speedup vs baseline: 1.7797x; 1.0100x over previous
#include <cuda_runtime.h>
#include <cuda_fp16.h>
#include <math.h>
#include <stdint.h>

// ---------------- problem constants ----------------
#define BB     2
#define SEQ    2048
#define DMODEL 2048
#define HKN    16
#define HVN    32
#define DKD    128
#define DVD    128
#define KDIM   2048
#define VDIM   4096
#define CONVD  8192
#define BSTOK  (BB*SEQ)

// ---------------- scratch ----------------
__device__ float  g_mixed[(size_t)BSTOK * CONVD];
__device__ float  g_z    [(size_t)BSTOK * VDIM];
__device__ float  g_q    [(size_t)BSTOK * KDIM];
__device__ float  g_k    [(size_t)BSTOK * KDIM];
__device__ float  g_v    [(size_t)BSTOK * VDIM];
__device__ float  g_eg   [(size_t)BSTOK * HVN];
__device__ float  g_beta [(size_t)BSTOK * HVN];
__device__ float  g_core [(size_t)BSTOK * VDIM];
// fp16 GEMM operands; weights stored TRANSPOSED (K-major: [N, K])
__device__ __half g_xh   [(size_t)BSTOK * DMODEL];
__device__ __half g_wqkvh[(size_t)CONVD * DMODEL];
__device__ __half g_wzh  [(size_t)VDIM * DMODEL];
__device__ __half g_wouth[(size_t)DMODEL * VDIM];
__device__ __half g_coreh[(size_t)BSTOK * VDIM];

// ---------------- ptx helpers ----------------
__device__ __forceinline__ uint32_t smem_u32(const void* p) {
    return (uint32_t)__cvta_generic_to_shared(p);
}
__device__ __forceinline__ void cp16(uint32_t saddr, const void* g) {
    asm volatile("cp.async.cg.shared.global [%0], [%1], 16;\n" :: "r"(saddr), "l"(g));
}
__device__ __forceinline__ void cp_commit() { asm volatile("cp.async.commit_group;\n"); }
template<int N> __device__ __forceinline__ void cp_wait() {
    asm volatile("cp.async.wait_group %0;\n" :: "n"(N));
}
__device__ __forceinline__ void ldsm_x4(uint32_t* r, uint32_t addr) {
    asm volatile("ldmatrix.sync.aligned.m8n8.x4.shared.b16 {%0,%1,%2,%3}, [%4];"
                 : "=r"(r[0]), "=r"(r[1]), "=r"(r[2]), "=r"(r[3]) : "r"(addr));
}
__device__ __forceinline__ void mma16816(float* c, const uint32_t* a, const uint32_t* b) {
    asm volatile(
        "mma.sync.aligned.m16n8k16.row.col.f32.f16.f16.f32 "
        "{%0,%1,%2,%3}, {%4,%5,%6,%7}, {%8,%9}, {%0,%1,%2,%3};"
        : "+f"(c[0]), "+f"(c[1]), "+f"(c[2]), "+f"(c[3])
        : "r"(a[0]), "r"(a[1]), "r"(a[2]), "r"(a[3]), "r"(b[0]), "r"(b[1]));
}

// =====================================================================
// fp16 GEMM: C[M,N] = A[M,K] @ Bt[N,K]^T, fp32 accum. (round-7 proven)
// CTA tile 128x256, warp tile 64x64 (8 warps), BK=64 (SW128 rows),
// 4-stage cp.async pipeline, ONE __syncthreads per K-tile.
// =====================================================================
#define NSTAGE 4
#define A_STAGE_BYTES 16384
#define B_STAGE_BYTES 32768
#define STAGE_BYTES   (A_STAGE_BYTES + B_STAGE_BYTES)
#define GEMM_DYN (NSTAGE*STAGE_BYTES + 1024)

__global__ __launch_bounds__(256, 1) void gemm_fp16(
    const __half* __restrict__ A, const __half* __restrict__ Bt,
    float* __restrict__ C, int M, int N, int K)
{
    extern __shared__ __align__(16) uint8_t dyn[];
    const uint32_t dynb = smem_u32(dyn);
    const uint32_t base = (dynb + 1023u) & ~1023u;

    const int tid  = threadIdx.x;
    const int wid  = tid >> 5;
    const int lane = tid & 31;
    const int bm0 = blockIdx.y * 128;
    const int bn0 = blockIdx.x * 256;
    const int wm  = (wid & 1) * 64;
    const int wn  = (wid >> 1) * 64;
    const int KT  = K >> 6;

    const __half* Arow = A  + (size_t)bm0 * K;
    const __half* Brow = Bt + (size_t)bn0 * K;

    auto load_tile = [&](int buf, int kt) {
        const uint32_t ab = base + buf * STAGE_BYTES;
        const uint32_t bb = ab + A_STAGE_BYTES;
        const int k0 = kt << 6;
        #pragma unroll
        for (int t = 0; t < 4; t++) {
            int c = tid + t * 256;
            int row = c >> 3;
            int cb  = (c & 7) << 4;
            uint32_t off = (uint32_t)(row * 128 + cb);
            uint32_t sw = off ^ ((off >> 3) & 0x70u);
            cp16(ab + sw, Arow + (size_t)row * K + k0 + (cb >> 1));
        }
        #pragma unroll
        for (int t = 0; t < 8; t++) {
            int c = tid + t * 256;
            int row = c >> 3;
            int cb  = (c & 7) << 4;
            uint32_t off = (uint32_t)(row * 128 + cb);
            uint32_t sw = off ^ ((off >> 3) & 0x70u);
            cp16(bb + sw, Brow + (size_t)row * K + k0 + (cb >> 1));
        }
        cp_commit();
    };

    const int aRowL = lane & 15;
    const int aKH2  = (lane >> 4) * 16;
    const int bRowL = ((lane >> 4) & 1) * 8 + (lane & 7);
    const int bKH2  = ((lane >> 3) & 1) * 16;

    float acc[4][8][4];
    #pragma unroll
    for (int i = 0; i < 4; i++)
        #pragma unroll
        for (int j = 0; j < 8; j++)
            #pragma unroll
            for (int q = 0; q < 4; q++) acc[i][j][q] = 0.0f;

    load_tile(0, 0);
    load_tile(1, KT > 1 ? 1 : 0);
    load_tile(2, KT > 2 ? 2 : 0);

    for (int i = 0; i < KT; i++) {
        cp_wait<2>();
        __syncthreads();

        if (i + 3 < KT) load_tile((i + 3) % NSTAGE, i + 3);
        else            cp_commit();

        const uint32_t ab = base + (i % NSTAGE) * STAGE_BYTES;
        const uint32_t bb = ab + A_STAGE_BYTES;

        #pragma unroll
        for (int ks = 0; ks < 4; ks++) {
            uint32_t af[4][4];
            uint32_t bf[4][4];
            #pragma unroll
            for (int mi = 0; mi < 4; mi++) {
                int row = wm + mi * 16 + aRowL;
                uint32_t cb = (uint32_t)((ks * 32 + aKH2) ^ ((row & 7) << 4));
                ldsm_x4(af[mi], ab + row * 128 + cb);
            }
            #pragma unroll
            for (int ni2 = 0; ni2 < 4; ni2++) {
                int row = wn + ni2 * 16 + bRowL;
                uint32_t cb = (uint32_t)((ks * 32 + bKH2) ^ ((row & 7) << 4));
                ldsm_x4(bf[ni2], bb + row * 128 + cb);
            }
            #pragma unroll
            for (int mi = 0; mi < 4; mi++)
                #pragma unroll
                for (int ni = 0; ni < 8; ni++)
                    mma16816(acc[mi][ni], af[mi], &bf[ni >> 1][(ni & 1) * 2]);
        }
    }

    const int l4 = lane >> 2;
    const int l2 = (lane & 3) * 2;
    #pragma unroll
    for (int mi = 0; mi < 4; mi++) {
        #pragma unroll
        for (int ni = 0; ni < 8; ni++) {
            float* c = acc[mi][ni];
            size_t r = (size_t)(bm0 + wm + mi * 16 + l4) * N + bn0 + wn + ni * 8 + l2;
            *(float2*)(C + r)                 = make_float2(c[0], c[1]);
            *(float2*)(C + r + 8 * (size_t)N) = make_float2(c[2], c[3]);
        }
    }
}

// =====================================================================
// prep kernels
// =====================================================================
__global__ __launch_bounds__(256) void round_f16_kernel(
    const float* __restrict__ src, __half* __restrict__ dst, int n4)
{
    int i = blockIdx.x * 256 + threadIdx.x;
    if (i < n4) {
        float4 v = ((const float4*)src)[i];
        ((__half2*)dst)[i * 2]     = __floats2half2_rn(v.x, v.y);
        ((__half2*)dst)[i * 2 + 1] = __floats2half2_rn(v.z, v.w);
    }
}

__global__ __launch_bounds__(256) void transpose_f16(
    const float* __restrict__ src, __half* __restrict__ dst, int K, int N)
{
    __shared__ float tile[32][33];
    const int n0 = blockIdx.x * 32, k0 = blockIdx.y * 32;
    const int tx = threadIdx.x & 31, ty = threadIdx.x >> 5;
    #pragma unroll
    for (int j = 0; j < 32; j += 8)
        tile[ty + j][tx] = src[(size_t)(k0 + ty + j) * N + n0 + tx];
    __syncthreads();
    #pragma unroll
    for (int j = 0; j < 32; j += 8)
        dst[(size_t)(n0 + ty + j) * K + k0 + tx] = __float2half_rn(tile[tx][ty + j]);
}

// =====================================================================
// b/a projections -> beta, exp(g)
// =====================================================================
__global__ __launch_bounds__(256) void proj_ba_kernel(
    const float* __restrict__ X, const float* __restrict__ wb,
    const float* __restrict__ wa, const float* __restrict__ dt_bias,
    const float* __restrict__ A_log,
    float* __restrict__ beta, float* __restrict__ eg)
{
    __shared__ float xs[DMODEL];
    const int bs = blockIdx.x;
    const int tid = threadIdx.x;
    for (int t = tid; t < DMODEL; t += 256)
        xs[t] = X[(size_t)bs * DMODEL + t];
    __syncthreads();

    const int out  = tid >> 2;
    const int part = tid & 3;
    const bool is_b = (out < 32);
    const int h = is_b ? out : out - 32;
    const float* w = (is_b ? wb : wa) + h;

    float acc = 0.0f;
    #pragma unroll 8
    for (int d = part; d < DMODEL; d += 4)
        acc += xs[d] * w[d * 32];
    acc += __shfl_xor_sync(0xffffffffu, acc, 1);
    acc += __shfl_xor_sync(0xffffffffu, acc, 2);

    if (part == 0) {
        if (is_b) {
            beta[(size_t)bs * HVN + h] = 1.0f / (1.0f + expf(-acc));
        } else {
            float x = acc + dt_bias[h];
            float sp = (x > 20.0f) ? x : log1pf(expf(x));
            eg[(size_t)bs * HVN + h] = expf(-expf(A_log[h]) * sp);
        }
    }
}

// =====================================================================
// conv1d(K=4, causal) + silu + per-head l2norm for q and k.
// =====================================================================
__global__ __launch_bounds__(128) void conv_qk_kernel(const float* __restrict__ conv_w)
{
    const int bs  = blockIdx.x;
    const int hy  = blockIdx.y;
    const bool is_k = (hy >= HKN);
    const int head  = is_k ? hy - HKN : hy;
    const int lane  = threadIdx.x;
    const int c     = (is_k ? KDIM : 0) + head * DKD + lane;
    const int s     = bs % SEQ;

    const float w0 = conv_w[c * 4 + 0];
    const float w1 = conv_w[c * 4 + 1];
    const float w2 = conv_w[c * 4 + 2];
    const float w3 = conv_w[c * 4 + 3];

    const long bsl = bs;
    float acc = w3 * g_mixed[bsl * CONVD + c];
    if (s > 0) acc += w2 * g_mixed[(bsl - 1) * CONVD + c];
    if (s > 1) acc += w1 * g_mixed[(bsl - 2) * CONVD + c];
    if (s > 2) acc += w0 * g_mixed[(bsl - 3) * CONVD + c];

    float val = acc / (1.0f + expf(-acc));

    float ss2 = val * val;
    #pragma unroll
    for (int o = 16; o > 0; o >>= 1)
        ss2 += __shfl_xor_sync(0xffffffffu, ss2, o);
    __shared__ float red[4];
    if ((lane & 31) == 0) red[lane >> 5] = ss2;
    __syncthreads();
    float tot = red[0] + red[1] + red[2] + red[3];

    float out = val * rsqrtf(tot + 1e-6f);
    if (!is_k) out *= 0.08838834764831845f;

    float* dst = is_k ? g_k : g_q;
    dst[(size_t)bs * KDIM + head * DKD + lane] = out;
}

// =====================================================================
// conv1d + silu for v channels.
// =====================================================================
__global__ __launch_bounds__(256) void conv_v_kernel(const float* __restrict__ conv_w)
{
    const size_t idx = (size_t)blockIdx.x * 256 + threadIdx.x;
    const int cv = (int)(idx % VDIM);
    const long bsl = (long)(idx / VDIM);
    const int s = (int)(bsl % SEQ);
    const int c = 2 * KDIM + cv;

    const float w0 = conv_w[c * 4 + 0];
    const float w1 = conv_w[c * 4 + 1];
    const float w2 = conv_w[c * 4 + 2];
    const float w3 = conv_w[c * 4 + 3];

    float acc = w3 * g_mixed[bsl * CONVD + c];
    if (s > 0) acc += w2 * g_mixed[(bsl - 1) * CONVD + c];
    if (s > 1) acc += w1 * g_mixed[(bsl - 2) * CONVD + c];
    if (s > 2) acc += w0 * g_mixed[(bsl - 3) * CONVD + c];

    g_v[idx] = acc / (1.0f + expf(-acc));
}

// =====================================================================
// Gated delta-rule scan (unchanged, proven).
// =====================================================================
__global__ __launch_bounds__(256) void scan_kernel()
{
    const int blk  = blockIdx.x;
    const int half = blk & 1;
    const int hv   = (blk >> 1) & (HVN - 1);
    const int b    = blk >> 6;
    const int kh   = hv >> 1;
    const int tid  = threadIdx.x;
    const int vcol = tid >> 2;
    const int s4   = tid & 3;

    __shared__ __align__(16) float sk[2][DKD];
    __shared__ __align__(16) float sq[2][DKD];
    __shared__ float sv[2][64];
    __shared__ float sgb[2][2];

    float St[32];
    #pragma unroll
    for (int i = 0; i < 32; i++) St[i] = 0.0f;

    const size_t bs0 = (size_t)b * SEQ;
    float rA = 0.0f, rV = 0.0f, rG = 0.0f, rB = 0.0f;

    {
        const size_t bs = bs0;
        if (tid < 128) rA = g_k[(bs * HKN + kh) * DKD + tid];
        else           rA = g_q[(bs * HKN + kh) * DKD + (tid - 128)];
        if (tid < 64)  rV = g_v[(bs * HVN + hv) * DVD + half * 64 + tid];
        if (tid == 0) { rG = g_eg[bs * HVN + hv]; rB = g_beta[bs * HVN + hv]; }
        if (tid < 128) sk[0][tid] = rA; else sq[0][tid - 128] = rA;
        if (tid < 64)  sv[0][tid] = rV;
        if (tid == 0) { sgb[0][0] = rG; sgb[0][1] = rB; }
    }
    __syncthreads();

    for (int s = 0; s < SEQ; s++) {
        const int p = s & 1;

        const bool more = (s + 1 < SEQ);
        if (more) {
            const size_t bs = bs0 + s + 1;
            if (tid < 128) rA = g_k[(bs * HKN + kh) * DKD + tid];
            else           rA = g_q[(bs * HKN + kh) * DKD + (tid - 128)];
            if (tid < 64)  rV = g_v[(bs * HVN + hv) * DVD + half * 64 + tid];
            if (tid == 0) { rG = g_eg[bs * HVN + hv]; rB = g_beta[bs * HVN + hv]; }
        }

        const float egv = sgb[p][0];
        const float bt  = sgb[p][1];
        const float4* k4 = (const float4*)(sk[p] + s4 * 32);
        const float4* q4 = (const float4*)(sq[p] + s4 * 32);

        float v0 = 0.f, v1 = 0.f, v2 = 0.f, v3 = 0.f;
        #pragma unroll
        for (int j = 0; j < 8; j++) {
            float4 kk = k4[j];
            St[4*j+0] *= egv; v0 += kk.x * St[4*j+0];
            St[4*j+1] *= egv; v1 += kk.y * St[4*j+1];
            St[4*j+2] *= egv; v2 += kk.z * St[4*j+2];
            St[4*j+3] *= egv; v3 += kk.w * St[4*j+3];
        }
        float vold = (v0 + v1) + (v2 + v3);
        vold += __shfl_xor_sync(0xffffffffu, vold, 1);
        vold += __shfl_xor_sync(0xffffffffu, vold, 2);

        const float delta = (sv[p][vcol] - vold) * bt;

        float o0 = 0.f, o1 = 0.f, o2 = 0.f, o3 = 0.f;
        #pragma unroll
        for (int j = 0; j < 8; j++) {
            float4 kk = k4[j];
            float4 qq = q4[j];
            St[4*j+0] += kk.x * delta; o0 += qq.x * St[4*j+0];
            St[4*j+1] += kk.y * delta; o1 += qq.y * St[4*j+1];
            St[4*j+2] += kk.z * delta; o2 += qq.z * St[4*j+2];
            St[4*j+3] += kk.w * delta; o3 += qq.w * St[4*j+3];
        }
        float o = (o0 + o1) + (o2 + o3);
        o += __shfl_xor_sync(0xffffffffu, o, 1);
        o += __shfl_xor_sync(0xffffffffu, o, 2);

        if (s4 == 0)
            g_core[((bs0 + s) * HVN + hv) * DVD + half * 64 + vcol] = o;

        if (more) {
            const int np = p ^ 1;
            if (tid < 128) sk[np][tid] = rA; else sq[np][tid - 128] = rA;
            if (tid < 64)  sv[np][tid] = rV;
            if (tid == 0) { sgb[np][0] = rG; sgb[np][1] = rB; }
        }
        __syncthreads();
    }
}

// =====================================================================
// RMSNorm * norm_weight * silu(z) -> fp16 core (feeds GEMM3).
// =====================================================================
__global__ __launch_bounds__(128) void rmsnorm_gate_kernel(const float* __restrict__ nw)
{
    const size_t gidx = blockIdx.x;
    const int lane = threadIdx.x;
    const size_t off = gidx * DVD + lane;

    float c = g_core[off];
    float v2 = c * c;
    #pragma unroll
    for (int o = 16; o > 0; o >>= 1)
        v2 += __shfl_xor_sync(0xffffffffu, v2, o);
    __shared__ float red[4];
    if ((lane & 31) == 0) red[lane >> 5] = v2;
    __syncthreads();
    float mean = (red[0] + red[1] + red[2] + red[3]) * (1.0f / 128.0f);

    float z = g_z[off];
    float sz = z / (1.0f + expf(-z));
    float r = c * rsqrtf(mean + 1e-6f) * nw[lane] * sz;
    g_coreh[off] = __float2half_rn(r);
}

// =====================================================================
// launch — fork/join multi-stream schedule:
//   s0: preps -> gemm1 -> [evG1] -> convqk -> convv -> (wait evPJ) scan
//       -> (wait evG2) rmsnorm -> gemm3
//   s1: (wait evPrep) proj_ba -> [evPJ] -> (wait evG1) gemm2 -> [evG2]
// gemm2 overlaps convs+scan on disjoint pipes.
// =====================================================================
extern "C" void kernel_launch(void* const* d_in, const int* in_sizes, int n_in,
                              void* d_out, int out_size)
{
    const float* X        = (const float*)d_in[0];
    const float* w_qkv    = (const float*)d_in[1];
    const float* w_z      = (const float*)d_in[2];
    const float* w_b      = (const float*)d_in[3];
    const float* w_a      = (const float*)d_in[4];
    const float* w_out    = (const float*)d_in[5];
    const float* conv_w   = (const float*)d_in[6];
    const float* dt_bias  = (const float*)d_in[7];
    const float* A_log    = (const float*)d_in[8];
    const float* norm_w   = (const float*)d_in[9];
    float* out = (float*)d_out;

    float  *p_mixed, *p_z, *p_eg, *p_beta;
    __half *p_xh, *p_wqkvh, *p_wzh, *p_wouth, *p_coreh;
    cudaGetSymbolAddress((void**)&p_mixed, g_mixed);
    cudaGetSymbolAddress((void**)&p_z,     g_z);
    cudaGetSymbolAddress((void**)&p_eg,    g_eg);
    cudaGetSymbolAddress((void**)&p_beta,  g_beta);
    cudaGetSymbolAddress((void**)&p_xh,    g_xh);
    cudaGetSymbolAddress((void**)&p_wqkvh, g_wqkvh);
    cudaGetSymbolAddress((void**)&p_wzh,   g_wzh);
    cudaGetSymbolAddress((void**)&p_wouth, g_wouth);
    cudaGetSymbolAddress((void**)&p_coreh, g_coreh);

    cudaFuncSetAttribute(gemm_fp16, cudaFuncAttributeMaxDynamicSharedMemorySize, GEMM_DYN);

    // side stream + events (created fresh each call; host-side only, no device mem)
    cudaStream_t s1;
    cudaStreamCreateWithFlags(&s1, cudaStreamNonBlocking);
    cudaEvent_t evPrep, evPJ, evG1, evG2;
    cudaEventCreateWithFlags(&evPrep, cudaEventDisableTiming);
    cudaEventCreateWithFlags(&evPJ,   cudaEventDisableTiming);
    cudaEventCreateWithFlags(&evG1,   cudaEventDisableTiming);
    cudaEventCreateWithFlags(&evG2,   cudaEventDisableTiming);

    // ---- s0: preps ----
    {
        int n4 = BSTOK * DMODEL / 4;
        round_f16_kernel<<<(n4 + 255) / 256, 256>>>(X, p_xh, n4);
        transpose_f16<<<dim3(CONVD / 32, DMODEL / 32), 256>>>(w_qkv, p_wqkvh, DMODEL, CONVD);
        transpose_f16<<<dim3(VDIM / 32, DMODEL / 32), 256>>>(w_z, p_wzh, DMODEL, VDIM);
        transpose_f16<<<dim3(DMODEL / 32, VDIM / 32), 256>>>(w_out, p_wouth, VDIM, DMODEL);
    }
    cudaEventRecord(evPrep, 0);            // fork point for s1

    // ---- s1: proj_ba (needs only X/w_b/w_a) ----
    cudaStreamWaitEvent(s1, evPrep, 0);
    proj_ba_kernel<<<BSTOK, 256, 0, s1>>>(X, w_b, w_a, dt_bias, A_log, p_beta, p_eg);
    cudaEventRecord(evPJ, s1);

    // ---- s0: gemm1 ----
    gemm_fp16<<<dim3(CONVD / 256, BSTOK / 128), 256, GEMM_DYN>>>(
        p_xh, p_wqkvh, p_mixed, BSTOK, CONVD, DMODEL);
    cudaEventRecord(evG1, 0);

    // ---- s1: gemm2 starts when gemm1 done; overlaps convs + scan on s0 ----
    cudaStreamWaitEvent(s1, evG1, 0);
    gemm_fp16<<<dim3(VDIM / 256, BSTOK / 128), 256, GEMM_DYN, s1>>>(
        p_xh, p_wzh, p_z, BSTOK, VDIM, DMODEL);
    cudaEventRecord(evG2, s1);

    // ---- s0: convs -> scan ----
    conv_qk_kernel<<<dim3(BSTOK, 2 * HKN), 128>>>(conv_w);
    conv_v_kernel<<<(BSTOK * (size_t)VDIM) / 256, 256>>>(conv_w);
    cudaStreamWaitEvent(0, evPJ, 0);       // beta/eg ready
    scan_kernel<<<BB * HVN * 2, 256>>>();

    // ---- join: rmsnorm needs z (gemm2) ----
    cudaStreamWaitEvent(0, evG2, 0);
    rmsnorm_gate_kernel<<<BSTOK * HVN, 128>>>(norm_w);

    // ---- s0: gemm3 ----
    gemm_fp16<<<dim3(DMODEL / 256, BSTOK / 128), 256, GEMM_DYN>>>(
        p_coreh, p_wouth, out, BSTOK, DMODEL, VDIM);
}

// round 9
// speedup vs baseline: 1.9329x; 1.0860x over previous
#include <cuda_runtime.h>
#include <cuda_fp16.h>
#include <math.h>
#include <stdint.h>

// ---------------- problem constants ----------------
#define BB     2
#define SEQ    2048
#define DMODEL 2048
#define HKN    16
#define HVN    32
#define DKD    128
#define DVD    128
#define KDIM   2048
#define VDIM   4096
#define CONVD  8192
#define BSTOK  (BB*SEQ)

// ---------------- scratch ----------------
__device__ float  g_mixed[(size_t)BSTOK * CONVD];
__device__ float  g_z    [(size_t)BSTOK * VDIM];
__device__ float  g_q    [(size_t)BSTOK * KDIM];
__device__ float  g_k    [(size_t)BSTOK * KDIM];
__device__ float  g_v    [(size_t)BSTOK * VDIM];
__device__ float  g_eg   [(size_t)BSTOK * HVN];
__device__ float  g_beta [(size_t)BSTOK * HVN];
__device__ float  g_core [(size_t)BSTOK * VDIM];
__device__ __half g_xh   [(size_t)BSTOK * DMODEL];
__device__ __half g_wqkvh[(size_t)CONVD * DMODEL];
__device__ __half g_wzh  [(size_t)VDIM * DMODEL];
__device__ __half g_wouth[(size_t)DMODEL * VDIM];
__device__ __half g_coreh[(size_t)BSTOK * VDIM];

// ---------------- ptx helpers ----------------
__device__ __forceinline__ uint32_t smem_u32(const void* p) {
    return (uint32_t)__cvta_generic_to_shared(p);
}
__device__ __forceinline__ void cp16(uint32_t saddr, const void* g) {
    asm volatile("cp.async.cg.shared.global [%0], [%1], 16;\n" :: "r"(saddr), "l"(g));
}
__device__ __forceinline__ void cp_commit() { asm volatile("cp.async.commit_group;\n"); }
template<int N> __device__ __forceinline__ void cp_wait() {
    asm volatile("cp.async.wait_group %0;\n" :: "n"(N));
}
__device__ __forceinline__ void ldsm_x4(uint32_t* r, uint32_t addr) {
    asm volatile("ldmatrix.sync.aligned.m8n8.x4.shared.b16 {%0,%1,%2,%3}, [%4];"
                 : "=r"(r[0]), "=r"(r[1]), "=r"(r[2]), "=r"(r[3]) : "r"(addr));
}
__device__ __forceinline__ void mma16816(float* c, const uint32_t* a, const uint32_t* b) {
    asm volatile(
        "mma.sync.aligned.m16n8k16.row.col.f32.f16.f16.f32 "
        "{%0,%1,%2,%3}, {%4,%5,%6,%7}, {%8,%9}, {%0,%1,%2,%3};"
        : "+f"(c[0]), "+f"(c[1]), "+f"(c[2]), "+f"(c[3])
        : "r"(a[0]), "r"(a[1]), "r"(a[2]), "r"(a[3]), "r"(b[0]), "r"(b[1]));
}
// packed fp32x2 (FFMA2) — sm_100-family PTX
__device__ __forceinline__ unsigned long long f2fma(
    unsigned long long a, unsigned long long b, unsigned long long c) {
    unsigned long long d;
    asm("fma.rn.f32x2 %0, %1, %2, %3;" : "=l"(d) : "l"(a), "l"(b), "l"(c));
    return d;
}
__device__ __forceinline__ unsigned long long f2mul(
    unsigned long long a, unsigned long long b) {
    unsigned long long d;
    asm("mul.rn.f32x2 %0, %1, %2;" : "=l"(d) : "l"(a), "l"(b));
    return d;
}
__device__ __forceinline__ unsigned long long pack2(float x, float y) {
    unsigned long long r;
    asm("mov.b64 %0, {%1, %2};" : "=l"(r) : "r"(__float_as_uint(x)), "r"(__float_as_uint(y)));
    return r;
}
__device__ __forceinline__ float hsum2(unsigned long long v) {
    uint32_t lo, hi;
    asm("mov.b64 {%0, %1}, %2;" : "=r"(lo), "=r"(hi) : "l"(v));
    return __uint_as_float(lo) + __uint_as_float(hi);
}

// =====================================================================
// fp16 GEMM (round-7 proven): CTA 128x256, warp 64x64, BK=64, 4-stage.
// =====================================================================
#define NSTAGE 4
#define A_STAGE_BYTES 16384
#define B_STAGE_BYTES 32768
#define STAGE_BYTES   (A_STAGE_BYTES + B_STAGE_BYTES)
#define GEMM_DYN (NSTAGE*STAGE_BYTES + 1024)

__global__ __launch_bounds__(256, 1) void gemm_fp16(
    const __half* __restrict__ A, const __half* __restrict__ Bt,
    float* __restrict__ C, int M, int N, int K)
{
    extern __shared__ __align__(16) uint8_t dyn[];
    const uint32_t dynb = smem_u32(dyn);
    const uint32_t base = (dynb + 1023u) & ~1023u;

    const int tid  = threadIdx.x;
    const int wid  = tid >> 5;
    const int lane = tid & 31;
    const int bm0 = blockIdx.y * 128;
    const int bn0 = blockIdx.x * 256;
    const int wm  = (wid & 1) * 64;
    const int wn  = (wid >> 1) * 64;
    const int KT  = K >> 6;

    const __half* Arow = A  + (size_t)bm0 * K;
    const __half* Brow = Bt + (size_t)bn0 * K;

    auto load_tile = [&](int buf, int kt) {
        const uint32_t ab = base + buf * STAGE_BYTES;
        const uint32_t bb = ab + A_STAGE_BYTES;
        const int k0 = kt << 6;
        #pragma unroll
        for (int t = 0; t < 4; t++) {
            int c = tid + t * 256;
            int row = c >> 3;
            int cb  = (c & 7) << 4;
            uint32_t off = (uint32_t)(row * 128 + cb);
            uint32_t sw = off ^ ((off >> 3) & 0x70u);
            cp16(ab + sw, Arow + (size_t)row * K + k0 + (cb >> 1));
        }
        #pragma unroll
        for (int t = 0; t < 8; t++) {
            int c = tid + t * 256;
            int row = c >> 3;
            int cb  = (c & 7) << 4;
            uint32_t off = (uint32_t)(row * 128 + cb);
            uint32_t sw = off ^ ((off >> 3) & 0x70u);
            cp16(bb + sw, Brow + (size_t)row * K + k0 + (cb >> 1));
        }
        cp_commit();
    };

    const int aRowL = lane & 15;
    const int aKH2  = (lane >> 4) * 16;
    const int bRowL = ((lane >> 4) & 1) * 8 + (lane & 7);
    const int bKH2  = ((lane >> 3) & 1) * 16;

    float acc[4][8][4];
    #pragma unroll
    for (int i = 0; i < 4; i++)
        #pragma unroll
        for (int j = 0; j < 8; j++)
            #pragma unroll
            for (int q = 0; q < 4; q++) acc[i][j][q] = 0.0f;

    load_tile(0, 0);
    load_tile(1, KT > 1 ? 1 : 0);
    load_tile(2, KT > 2 ? 2 : 0);

    for (int i = 0; i < KT; i++) {
        cp_wait<2>();
        __syncthreads();

        if (i + 3 < KT) load_tile((i + 3) % NSTAGE, i + 3);
        else            cp_commit();

        const uint32_t ab = base + (i % NSTAGE) * STAGE_BYTES;
        const uint32_t bb = ab + A_STAGE_BYTES;

        #pragma unroll
        for (int ks = 0; ks < 4; ks++) {
            uint32_t af[4][4];
            uint32_t bf[4][4];
            #pragma unroll
            for (int mi = 0; mi < 4; mi++) {
                int row = wm + mi * 16 + aRowL;
                uint32_t cb = (uint32_t)((ks * 32 + aKH2) ^ ((row & 7) << 4));
                ldsm_x4(af[mi], ab + row * 128 + cb);
            }
            #pragma unroll
            for (int ni2 = 0; ni2 < 4; ni2++) {
                int row = wn + ni2 * 16 + bRowL;
                uint32_t cb = (uint32_t)((ks * 32 + bKH2) ^ ((row & 7) << 4));
                ldsm_x4(bf[ni2], bb + row * 128 + cb);
            }
            #pragma unroll
            for (int mi = 0; mi < 4; mi++)
                #pragma unroll
                for (int ni = 0; ni < 8; ni++)
                    mma16816(acc[mi][ni], af[mi], &bf[ni >> 1][(ni & 1) * 2]);
        }
    }

    const int l4 = lane >> 2;
    const int l2 = (lane & 3) * 2;
    #pragma unroll
    for (int mi = 0; mi < 4; mi++) {
        #pragma unroll
        for (int ni = 0; ni < 8; ni++) {
            float* c = acc[mi][ni];
            size_t r = (size_t)(bm0 + wm + mi * 16 + l4) * N + bn0 + wn + ni * 8 + l2;
            *(float2*)(C + r)                 = make_float2(c[0], c[1]);
            *(float2*)(C + r + 8 * (size_t)N) = make_float2(c[2], c[3]);
        }
    }
}

// =====================================================================
// prep kernels
// =====================================================================
__global__ __launch_bounds__(256) void round_f16_kernel(
    const float* __restrict__ src, __half* __restrict__ dst, int n4)
{
    int i = blockIdx.x * 256 + threadIdx.x;
    if (i < n4) {
        float4 v = ((const float4*)src)[i];
        ((__half2*)dst)[i * 2]     = __floats2half2_rn(v.x, v.y);
        ((__half2*)dst)[i * 2 + 1] = __floats2half2_rn(v.z, v.w);
    }
}

__global__ __launch_bounds__(256) void transpose_f16(
    const float* __restrict__ src, __half* __restrict__ dst, int K, int N)
{
    __shared__ float tile[32][33];
    const int n0 = blockIdx.x * 32, k0 = blockIdx.y * 32;
    const int tx = threadIdx.x & 31, ty = threadIdx.x >> 5;
    #pragma unroll
    for (int j = 0; j < 32; j += 8)
        tile[ty + j][tx] = src[(size_t)(k0 + ty + j) * N + n0 + tx];
    __syncthreads();
    #pragma unroll
    for (int j = 0; j < 32; j += 8)
        dst[(size_t)(n0 + ty + j) * K + k0 + tx] = __float2half_rn(tile[tx][ty + j]);
}

// =====================================================================
// b/a projections -> beta, exp(g)
// =====================================================================
__global__ __launch_bounds__(256) void proj_ba_kernel(
    const float* __restrict__ X, const float* __restrict__ wb,
    const float* __restrict__ wa, const float* __restrict__ dt_bias,
    const float* __restrict__ A_log,
    float* __restrict__ beta, float* __restrict__ eg)
{
    __shared__ float xs[DMODEL];
    const int bs = blockIdx.x;
    const int tid = threadIdx.x;
    for (int t = tid; t < DMODEL; t += 256)
        xs[t] = X[(size_t)bs * DMODEL + t];
    __syncthreads();

    const int out  = tid >> 2;
    const int part = tid & 3;
    const bool is_b = (out < 32);
    const int h = is_b ? out : out - 32;
    const float* w = (is_b ? wb : wa) + h;

    float acc = 0.0f;
    #pragma unroll 8
    for (int d = part; d < DMODEL; d += 4)
        acc += xs[d] * w[d * 32];
    acc += __shfl_xor_sync(0xffffffffu, acc, 1);
    acc += __shfl_xor_sync(0xffffffffu, acc, 2);

    if (part == 0) {
        if (is_b) {
            beta[(size_t)bs * HVN + h] = 1.0f / (1.0f + expf(-acc));
        } else {
            float x = acc + dt_bias[h];
            float sp = (x > 20.0f) ? x : log1pf(expf(x));
            eg[(size_t)bs * HVN + h] = expf(-expf(A_log[h]) * sp);
        }
    }
}

// =====================================================================
// conv1d(K=4, causal) + silu + per-head l2norm for q and k.
// =====================================================================
__global__ __launch_bounds__(128) void conv_qk_kernel(const float* __restrict__ conv_w)
{
    const int bs  = blockIdx.x;
    const int hy  = blockIdx.y;
    const bool is_k = (hy >= HKN);
    const int head  = is_k ? hy - HKN : hy;
    const int lane  = threadIdx.x;
    const int c     = (is_k ? KDIM : 0) + head * DKD + lane;
    const int s     = bs % SEQ;

    const float w0 = conv_w[c * 4 + 0];
    const float w1 = conv_w[c * 4 + 1];
    const float w2 = conv_w[c * 4 + 2];
    const float w3 = conv_w[c * 4 + 3];

    const long bsl = bs;
    float acc = w3 * g_mixed[bsl * CONVD + c];
    if (s > 0) acc += w2 * g_mixed[(bsl - 1) * CONVD + c];
    if (s > 1) acc += w1 * g_mixed[(bsl - 2) * CONVD + c];
    if (s > 2) acc += w0 * g_mixed[(bsl - 3) * CONVD + c];

    float val = acc / (1.0f + expf(-acc));

    float ss2 = val * val;
    #pragma unroll
    for (int o = 16; o > 0; o >>= 1)
        ss2 += __shfl_xor_sync(0xffffffffu, ss2, o);
    __shared__ float red[4];
    if ((lane & 31) == 0) red[lane >> 5] = ss2;
    __syncthreads();
    float tot = red[0] + red[1] + red[2] + red[3];

    float out = val * rsqrtf(tot + 1e-6f);
    if (!is_k) out *= 0.08838834764831845f;

    float* dst = is_k ? g_k : g_q;
    dst[(size_t)bs * KDIM + head * DKD + lane] = out;
}

// =====================================================================
// conv1d + silu for v channels.
// =====================================================================
__global__ __launch_bounds__(256) void conv_v_kernel(const float* __restrict__ conv_w)
{
    const size_t idx = (size_t)blockIdx.x * 256 + threadIdx.x;
    const int cv = (int)(idx % VDIM);
    const long bsl = (long)(idx / VDIM);
    const int s = (int)(bsl % SEQ);
    const int c = 2 * KDIM + cv;

    const float w0 = conv_w[c * 4 + 0];
    const float w1 = conv_w[c * 4 + 1];
    const float w2 = conv_w[c * 4 + 2];
    const float w3 = conv_w[c * 4 + 3];

    float acc = w3 * g_mixed[bsl * CONVD + c];
    if (s > 0) acc += w2 * g_mixed[(bsl - 1) * CONVD + c];
    if (s > 1) acc += w1 * g_mixed[(bsl - 2) * CONVD + c];
    if (s > 2) acc += w0 * g_mixed[(bsl - 3) * CONVD + c];

    g_v[idx] = acc / (1.0f + expf(-acc));
}

// =====================================================================
// Gated delta-rule scan, packed f32x2 math.
// 256 CTAs (b, hv, quarter of DV), 128 threads (coresidency-friendly).
// thread: vcol = tid>>2 (0..31 in quarter), s4 = tid&3 (32 k-rows).
// vold = egv * (k . S_old);  S = egv*S + k*delta;  o = q . S.
// =====================================================================
__global__ __launch_bounds__(128) void scan_kernel()
{
    const int blk  = blockIdx.x;
    const int quar = blk & 3;
    const int hv   = (blk >> 2) & (HVN - 1);
    const int b    = blk >> 7;
    const int kh   = hv >> 1;
    const int tid  = threadIdx.x;
    const int vcol = tid >> 2;
    const int s4   = tid & 3;

    __shared__ __align__(16) float sk[2][DKD];
    __shared__ __align__(16) float sq[2][DKD];
    __shared__ float sv[2][32];
    __shared__ float sgb[2][2];

    unsigned long long St2[16];
    #pragma unroll
    for (int i = 0; i < 16; i++) St2[i] = 0ull;

    const size_t bs0 = (size_t)b * SEQ;
    float rK = 0.f, rQ = 0.f, rV = 0.f, rG = 0.f, rB = 0.f;

    {
        const size_t bs = bs0;
        rK = g_k[(bs * HKN + kh) * DKD + tid];
        rQ = g_q[(bs * HKN + kh) * DKD + tid];
        if (tid < 32) rV = g_v[(bs * HVN + hv) * DVD + quar * 32 + tid];
        if (tid == 0) { rG = g_eg[bs * HVN + hv]; rB = g_beta[bs * HVN + hv]; }
        sk[0][tid] = rK; sq[0][tid] = rQ;
        if (tid < 32) sv[0][tid] = rV;
        if (tid == 0) { sgb[0][0] = rG; sgb[0][1] = rB; }
    }
    __syncthreads();

    for (int s = 0; s < SEQ; s++) {
        const int p = s & 1;

        const bool more = (s + 1 < SEQ);
        if (more) {
            const size_t bs = bs0 + s + 1;
            rK = g_k[(bs * HKN + kh) * DKD + tid];
            rQ = g_q[(bs * HKN + kh) * DKD + tid];
            if (tid < 32) rV = g_v[(bs * HVN + hv) * DVD + quar * 32 + tid];
            if (tid == 0) { rG = g_eg[bs * HVN + hv]; rB = g_beta[bs * HVN + hv]; }
        }

        const float egv = sgb[p][0];
        const float bt  = sgb[p][1];
        const unsigned long long* k2 = (const unsigned long long*)(sk[p] + s4 * 32);
        const unsigned long long* q2 = (const unsigned long long*)(sq[p] + s4 * 32);

        // vold = egv * (k . S_old)
        unsigned long long d0 = 0ull, d1 = 0ull, d2 = 0ull, d3 = 0ull;
        #pragma unroll
        for (int j = 0; j < 4; j++) {
            d0 = f2fma(k2[4*j+0], St2[4*j+0], d0);
            d1 = f2fma(k2[4*j+1], St2[4*j+1], d1);
            d2 = f2fma(k2[4*j+2], St2[4*j+2], d2);
            d3 = f2fma(k2[4*j+3], St2[4*j+3], d3);
        }
        float vold = egv * ((hsum2(d0) + hsum2(d1)) + (hsum2(d2) + hsum2(d3)));
        vold += __shfl_xor_sync(0xffffffffu, vold, 1);
        vold += __shfl_xor_sync(0xffffffffu, vold, 2);

        const float delta = (sv[p][vcol] - vold) * bt;
        const unsigned long long delta2 = pack2(delta, delta);
        const unsigned long long eg2    = pack2(egv, egv);

        // S = egv*S + k*delta;  o = q . S
        unsigned long long o0 = 0ull, o1 = 0ull, o2 = 0ull, o3 = 0ull;
        #pragma unroll
        for (int j = 0; j < 4; j++) {
            unsigned long long kd;
            kd = f2mul(k2[4*j+0], delta2); St2[4*j+0] = f2fma(eg2, St2[4*j+0], kd);
            o0 = f2fma(q2[4*j+0], St2[4*j+0], o0);
            kd = f2mul(k2[4*j+1], delta2); St2[4*j+1] = f2fma(eg2, St2[4*j+1], kd);
            o1 = f2fma(q2[4*j+1], St2[4*j+1], o1);
            kd = f2mul(k2[4*j+2], delta2); St2[4*j+2] = f2fma(eg2, St2[4*j+2], kd);
            o2 = f2fma(q2[4*j+2], St2[4*j+2], o2);
            kd = f2mul(k2[4*j+3], delta2); St2[4*j+3] = f2fma(eg2, St2[4*j+3], kd);
            o3 = f2fma(q2[4*j+3], St2[4*j+3], o3);
        }
        float o = (hsum2(o0) + hsum2(o1)) + (hsum2(o2) + hsum2(o3));
        o += __shfl_xor_sync(0xffffffffu, o, 1);
        o += __shfl_xor_sync(0xffffffffu, o, 2);

        if (s4 == 0)
            g_core[((bs0 + s) * HVN + hv) * DVD + quar * 32 + vcol] = o;

        if (more) {
            const int np = p ^ 1;
            sk[np][tid] = rK; sq[np][tid] = rQ;
            if (tid < 32) sv[np][tid] = rV;
            if (tid == 0) { sgb[np][0] = rG; sgb[np][1] = rB; }
        }
        __syncthreads();
    }
}

// =====================================================================
// RMSNorm * norm_weight * silu(z) -> fp16 core (feeds GEMM3).
// =====================================================================
__global__ __launch_bounds__(128) void rmsnorm_gate_kernel(const float* __restrict__ nw)
{
    const size_t gidx = blockIdx.x;
    const int lane = threadIdx.x;
    const size_t off = gidx * DVD + lane;

    float c = g_core[off];
    float v2 = c * c;
    #pragma unroll
    for (int o = 16; o > 0; o >>= 1)
        v2 += __shfl_xor_sync(0xffffffffu, v2, o);
    __shared__ float red[4];
    if ((lane & 31) == 0) red[lane >> 5] = v2;
    __syncthreads();
    float mean = (red[0] + red[1] + red[2] + red[3]) * (1.0f / 128.0f);

    float z = g_z[off];
    float sz = z / (1.0f + expf(-z));
    float r = c * rsqrtf(mean + 1e-6f) * nw[lane] * sz;
    g_coreh[off] = __float2half_rn(r);
}

// =====================================================================
// launch — fork/join, minimal critical path:
//   s0: round(X), transpose(wqkv) -> gemm1 -> convs -> (evPJ) scan
//       -> (evG2) rmsnorm -> gemm3
//   s1: transpose(wz), transpose(wout), proj_ba [evPJ]
//       -> (evG1) gemm2 [evG2]   (overlaps convs+scan; scan CTAs coreside)
// =====================================================================
extern "C" void kernel_launch(void* const* d_in, const int* in_sizes, int n_in,
                              void* d_out, int out_size)
{
    const float* X        = (const float*)d_in[0];
    const float* w_qkv    = (const float*)d_in[1];
    const float* w_z      = (const float*)d_in[2];
    const float* w_b      = (const float*)d_in[3];
    const float* w_a      = (const float*)d_in[4];
    const float* w_out    = (const float*)d_in[5];
    const float* conv_w   = (const float*)d_in[6];
    const float* dt_bias  = (const float*)d_in[7];
    const float* A_log    = (const float*)d_in[8];
    const float* norm_w   = (const float*)d_in[9];
    float* out = (float*)d_out;

    float  *p_mixed, *p_z, *p_eg, *p_beta;
    __half *p_xh, *p_wqkvh, *p_wzh, *p_wouth, *p_coreh;
    cudaGetSymbolAddress((void**)&p_mixed, g_mixed);
    cudaGetSymbolAddress((void**)&p_z,     g_z);
    cudaGetSymbolAddress((void**)&p_eg,    g_eg);
    cudaGetSymbolAddress((void**)&p_beta,  g_beta);
    cudaGetSymbolAddress((void**)&p_xh,    g_xh);
    cudaGetSymbolAddress((void**)&p_wqkvh, g_wqkvh);
    cudaGetSymbolAddress((void**)&p_wzh,   g_wzh);
    cudaGetSymbolAddress((void**)&p_wouth, g_wouth);
    cudaGetSymbolAddress((void**)&p_coreh, g_coreh);

    cudaFuncSetAttribute(gemm_fp16, cudaFuncAttributeMaxDynamicSharedMemorySize, GEMM_DYN);

    cudaStream_t s1;
    cudaStreamCreateWithFlags(&s1, cudaStreamNonBlocking);
    cudaEvent_t evRoot, evPJ, evG1, evG2;
    cudaEventCreateWithFlags(&evRoot, cudaEventDisableTiming);
    cudaEventCreateWithFlags(&evPJ,   cudaEventDisableTiming);
    cudaEventCreateWithFlags(&evG1,   cudaEventDisableTiming);
    cudaEventCreateWithFlags(&evG2,   cudaEventDisableTiming);

    // fork root so s1 launches are ordered within the captured graph
    cudaEventRecord(evRoot, 0);
    cudaStreamWaitEvent(s1, evRoot, 0);

    // ---- s0: minimal prep for gemm1 ----
    {
        int n4 = BSTOK * DMODEL / 4;
        round_f16_kernel<<<(n4 + 255) / 256, 256>>>(X, p_xh, n4);
        transpose_f16<<<dim3(CONVD / 32, DMODEL / 32), 256>>>(w_qkv, p_wqkvh, DMODEL, CONVD);
    }

    // ---- s1: off-critical-path preps + proj ----
    transpose_f16<<<dim3(VDIM / 32, DMODEL / 32), 256, 0, s1>>>(w_z, p_wzh, DMODEL, VDIM);
    transpose_f16<<<dim3(DMODEL / 32, VDIM / 32), 256, 0, s1>>>(w_out, p_wouth, VDIM, DMODEL);
    proj_ba_kernel<<<BSTOK, 256, 0, s1>>>(X, w_b, w_a, dt_bias, A_log, p_beta, p_eg);
    cudaEventRecord(evPJ, s1);

    // ---- s0: gemm1 ----
    gemm_fp16<<<dim3(CONVD / 256, BSTOK / 128), 256, GEMM_DYN>>>(
        p_xh, p_wqkvh, p_mixed, BSTOK, CONVD, DMODEL);
    cudaEventRecord(evG1, 0);

    // ---- s1: gemm2 overlaps convs + scan ----
    cudaStreamWaitEvent(s1, evG1, 0);
    gemm_fp16<<<dim3(VDIM / 256, BSTOK / 128), 256, GEMM_DYN, s1>>>(
        p_xh, p_wzh, p_z, BSTOK, VDIM, DMODEL);
    cudaEventRecord(evG2, s1);

    // ---- s0: convs -> scan ----
    conv_qk_kernel<<<dim3(BSTOK, 2 * HKN), 128>>>(conv_w);
    conv_v_kernel<<<(BSTOK * (size_t)VDIM) / 256, 256>>>(conv_w);
    cudaStreamWaitEvent(0, evPJ, 0);
    scan_kernel<<<BB * HVN * 4, 128>>>();

    // ---- join: rmsnorm needs z ----
    cudaStreamWaitEvent(0, evG2, 0);
    rmsnorm_gate_kernel<<<BSTOK * HVN, 128>>>(norm_w);

    // ---- s0: gemm3 ----
    gemm_fp16<<<dim3(DMODEL / 256, BSTOK / 128), 256, GEMM_DYN>>>(
        p_coreh, p_wouth, out, BSTOK, DMODEL, VDIM);
}